// round 11
// baseline (speedup 1.0000x reference)
#include <cuda_runtime.h>
#include <cuda_bf16.h>
#include <cstdint>

// ============================================================================
// AdaptiveTokenFilter — GB300 sm_103a — 1-pass bf16 HMMA + exact 3-pass refine
// R11: main GEMM warp tile 64x64 (CTA 128x256) -> halves ldsm traffic per MAC,
// tensor pipe becomes sole binder. Tail identical to R10.
// ============================================================================

#define B_ 8
#define S_ 4096
#define D_ 1024
#define H_ 2048
#define M_ (B_ * S_)            // 32768 tokens
#define MAXK 64
#define CMAX 128                // max candidates per row
#define CTOT (B_ * CMAX)        // 1024 compact rows
#define DELTA 0.1f              // candidate window (>=8x max 1-pass error)

#define OUT_MASK_OFF ((size_t)M_ * D_)
#define OUT_EK_OFF   ((size_t)M_ * D_ + M_)

#define THREEFRY_PARTITIONABLE 1

#define BK_ 64
#define NKC (D_ / BK_)          // 16 k-chunks

// dynamic smem: both instantiations use 48KB/stage x 2 + align slack
#define SMEM_GEMM (2 * 49152 + 1024)   // 99328

#define SW128(bo) ((bo) ^ (((bo) >> 3) & 0x70))

// ------------------------- device scratch (no allocs) -----------------------
__device__ __nv_bfloat16 g_Xhi[(size_t)M_ * D_];
__device__ __nv_bfloat16 g_W1thi[(size_t)H_ * D_];
__device__ __nv_bfloat16 g_W1tlo[(size_t)H_ * D_];
__device__ __nv_bfloat16 g_Chi[(size_t)CTOT * D_];
__device__ __nv_bfloat16 g_Clo[(size_t)CTOT * D_];
__device__ float    g_pert[M_];            // main: logit partials (atomic)
__device__ float    g_cand_logit[CTOT];
__device__ int      g_cand_idx[CTOT];      // global token ids
__device__ int      g_cand_cnt[B_];
__device__ unsigned char g_sel[M_];
__device__ int      g_ksel;
__device__ uint32_t g_rng2k[2];

// ------------------------- PTX helpers --------------------------------------
__device__ __forceinline__ uint32_t smem_u32(const void* p) {
    uint32_t a;
    asm("{ .reg .u64 t; cvta.to.shared.u64 t, %1; cvt.u32.u64 %0, t; }" : "=r"(a) : "l"(p));
    return a;
}
#define CP16(dst, src) \
    asm volatile("cp.async.cg.shared.global [%0], [%1], 16;" \
        :: "r"((uint32_t)(dst)), "l"((const void*)(src)) : "memory")
#define CP_COMMIT() asm volatile("cp.async.commit_group;" ::: "memory")
#define CP_WAIT1()  asm volatile("cp.async.wait_group 1;" ::: "memory")
#define CP_WAIT0()  asm volatile("cp.async.wait_group 0;" ::: "memory")

__device__ __forceinline__ void ldsm_x4(uint32_t& r0, uint32_t& r1,
                                        uint32_t& r2, uint32_t& r3, uint32_t a) {
    asm volatile("ldmatrix.sync.aligned.m8n8.x4.shared.b16 {%0,%1,%2,%3}, [%4];"
                 : "=r"(r0), "=r"(r1), "=r"(r2), "=r"(r3) : "r"(a));
}
__device__ __forceinline__ void mma_bf16(float* c, const uint32_t* a, const uint32_t* b) {
    asm volatile("mma.sync.aligned.m16n8k16.row.col.f32.bf16.bf16.f32 "
                 "{%0,%1,%2,%3}, {%4,%5,%6,%7}, {%8,%9}, {%0,%1,%2,%3};"
                 : "+f"(c[0]), "+f"(c[1]), "+f"(c[2]), "+f"(c[3])
                 : "r"(a[0]), "r"(a[1]), "r"(a[2]), "r"(a[3]), "r"(b[0]), "r"(b[1]));
}

// ------------------------- threefry2x32 (JAX-exact, 20 rounds) --------------
__device__ __forceinline__ uint32_t rotl32(uint32_t v, int r) {
    return (v << r) | (v >> (32 - r));
}
__device__ __forceinline__ void tf_rounds_a(uint32_t& x0, uint32_t& x1) {
    x0 += x1; x1 = rotl32(x1, 13); x1 ^= x0;
    x0 += x1; x1 = rotl32(x1, 15); x1 ^= x0;
    x0 += x1; x1 = rotl32(x1, 26); x1 ^= x0;
    x0 += x1; x1 = rotl32(x1,  6); x1 ^= x0;
}
__device__ __forceinline__ void tf_rounds_b(uint32_t& x0, uint32_t& x1) {
    x0 += x1; x1 = rotl32(x1, 17); x1 ^= x0;
    x0 += x1; x1 = rotl32(x1, 29); x1 ^= x0;
    x0 += x1; x1 = rotl32(x1, 16); x1 ^= x0;
    x0 += x1; x1 = rotl32(x1, 24); x1 ^= x0;
}
__device__ __forceinline__ void threefry2x32(uint32_t k1, uint32_t k2,
                                             uint32_t x0, uint32_t x1,
                                             uint32_t* o0, uint32_t* o1) {
    uint32_t ks2 = k1 ^ k2 ^ 0x1BD11BDAu;
    x0 += k1; x1 += k2;
    tf_rounds_a(x0, x1); x0 += k2;  x1 += ks2 + 1u;
    tf_rounds_b(x0, x1); x0 += ks2; x1 += k1  + 2u;
    tf_rounds_a(x0, x1); x0 += k1;  x1 += k2  + 3u;
    tf_rounds_b(x0, x1); x0 += k2;  x1 += ks2 + 4u;
    tf_rounds_a(x0, x1); x0 += ks2; x1 += k1  + 5u;
    *o0 = x0; *o1 = x1;
}
__device__ __forceinline__ uint32_t jax_random_bits32(uint32_t k1, uint32_t k2,
                                                      uint32_t idx, uint32_t n) {
#if THREEFRY_PARTITIONABLE
    uint32_t o0, o1;
    threefry2x32(k1, k2, 0u, idx, &o0, &o1);
    return o0 ^ o1;
#else
    uint32_t half = n >> 1;
    uint32_t o0, o1;
    if (idx < half) { threefry2x32(k1, k2, idx, idx + half, &o0, &o1); return o0; }
    else            { threefry2x32(k1, k2, idx - half, idx, &o0, &o1); return o1; }
#endif
}
__device__ __forceinline__ float jax_gumbel(uint32_t k1, uint32_t k2,
                                            uint32_t idx, uint32_t n) {
    uint32_t bits = jax_random_bits32(k1, k2, idx, n);
    float f = __uint_as_float((bits >> 9) | 0x3f800000u) - 1.0f;
    const float minv = 1e-8f;
    float u = __fadd_rn(__fmul_rn(f, 1.0f - 1e-8f), minv);
    u = fmaxf(minv, u);
    return -logf(-logf(u));
}

// ------------------------- kernel: X -> bf16 hi (+ zero pert) ---------------
__global__ void convert_x_kernel(const float* __restrict__ X) {
    if (threadIdx.x == 0) g_pert[blockIdx.x] = 0.f;   // 1 block == 1 token row
    size_t i = ((size_t)blockIdx.x * blockDim.x + threadIdx.x) * 4;
    float4 v = *(const float4*)(X + i);
    __nv_bfloat162 hp0 = {__float2bfloat16(v.x), __float2bfloat16(v.y)};
    __nv_bfloat162 hp1 = {__float2bfloat16(v.z), __float2bfloat16(v.w)};
    *(uint2*)&g_Xhi[i] = make_uint2(*(uint32_t*)&hp0, *(uint32_t*)&hp1);
}

// ------------------------- kernel: tiled transpose+split W1 -----------------
__global__ void convert_w1_kernel(const float* __restrict__ W1) {
    __shared__ float tile[32][33];
    const int bn = blockIdx.x;            // H/32 = 64
    const int bk = blockIdx.y;            // D/32 = 32
    const int tx = threadIdx.x & 31;
    const int ty = threadIdx.x >> 5;      // 0..7
#pragma unroll
    for (int i = 0; i < 4; i++) {
        int k = bk * 32 + ty + i * 8;
        tile[ty + i * 8][tx] = W1[(size_t)k * H_ + bn * 32 + tx];
    }
    __syncthreads();
#pragma unroll
    for (int i = 0; i < 4; i++) {
        int n = bn * 32 + ty + i * 8;
        int k = bk * 32 + tx;
        float v = tile[tx][ty + i * 8];
        __nv_bfloat16 h = __float2bfloat16(v);
        __nv_bfloat16 l = __float2bfloat16(v - __bfloat162float(h));
        g_W1thi[(size_t)n * D_ + k] = h;
        g_W1tlo[(size_t)n * D_ + k] = l;
    }
}

// ------------------------- kernel: k-selection path -------------------------
__global__ void k_select_kernel(const float* __restrict__ k_logits,
                                float* __restrict__ out_ek) {
    __shared__ float vals[MAXK];
    __shared__ uint32_t rngs[4];
    if (threadIdx.x == 0) {
        uint32_t a, b;
#if THREEFRY_PARTITIONABLE
        threefry2x32(0u, 42u, 0u, 0u, &a, &b); rngs[0] = a; rngs[1] = b;
        threefry2x32(0u, 42u, 0u, 1u, &a, &b); rngs[2] = a; rngs[3] = b;
#else
        uint32_t a0, b0, a1, b1;
        threefry2x32(0u, 42u, 0u, 2u, &a0, &b0);
        threefry2x32(0u, 42u, 1u, 3u, &a1, &b1);
        rngs[0] = a0; rngs[1] = a1; rngs[2] = b0; rngs[3] = b1;
#endif
        g_rng2k[0] = rngs[2]; g_rng2k[1] = rngs[3];
    }
    __syncthreads();
    int i = threadIdx.x;
    float g = jax_gumbel(rngs[0], rngs[1], (uint32_t)i, MAXK);
    vals[i] = k_logits[i] + g;
    __syncthreads();
    if (i == 0) {
        float mx = vals[0]; int am = 0;
        for (int j = 1; j < MAXK; j++)
            if (vals[j] > mx) { mx = vals[j]; am = j; }
        float sum = 0.f, ek = 0.f;
        for (int j = 0; j < MAXK; j++) {
            float e = expf(vals[j] - mx);
            sum += e; ek += e * (float)(j + 1);
        }
        g_ksel = am + 1;
        out_ek[0] = ek / sum;
    }
}

// ------------------------- kernel: zero output (emb + mask) -----------------
__global__ void zero_out_kernel(float* __restrict__ out) {
    size_t i = ((size_t)blockIdx.x * 256 + threadIdx.x) * 4;
    *(float4*)(out + i) = make_float4(0.f, 0.f, 0.f, 0.f);
}

// ------------------------- templated HMMA GEMM (2-stage core) ---------------
// CTA tile BMp x BNp; one n-tile per CTA (blockIdx.y); 8 warps as 2m x 4n,
// warp tile (BMp/2) x (BNp/4). atomicAdd relu(A·W1t+b1)·W2 partial into outp.
template<int PASSES, int BMp, int BNp, int MINB>
__global__ void __launch_bounds__(256, MINB)
gemm_kernel(const __nv_bfloat16* __restrict__ Ahi,
            const __nv_bfloat16* __restrict__ Alo,
            const float* __restrict__ b1,
            const float* __restrict__ W2,
            float* __restrict__ outp) {
    extern __shared__ char dyn_smem[];
    __shared__ float red[BMp][4];

    constexpr int MT = BMp / 32;                      // A i-tiles per warp (16h)
    constexpr int JT = BNp / 32;                      // B j-tiles per warp (8w)
    constexpr uint32_t A_T  = (uint32_t)BMp * 128;
    constexpr uint32_t B_T  = (uint32_t)BNp * 128;
    constexpr uint32_t BH_O = (PASSES == 3) ? 2 * A_T : A_T;
    constexpr uint32_t BL_O = BH_O + B_T;
    constexpr uint32_t BUFB = BH_O + ((PASSES == 3) ? 2 : 1) * B_T;
    constexpr int AI = BMp * 8 / 256;                 // A loader iterations
    constexpr int BI = BNp * 8 / 256;                 // B loader iterations

    const uint32_t braw = smem_u32(dyn_smem);
    const uint32_t base = (braw + 1023u) & ~1023u;

    const int t   = threadIdx.x;
    const int l   = t & 31;
    const int wid = t >> 5;
    const int wm  = wid >> 2;      // 0..1
    const int wn  = wid & 3;       // 0..3
    const int m0  = blockIdx.x * BMp;
    const int nt  = blockIdx.y;

    float rowacc[MT][2];
#pragma unroll
    for (int i = 0; i < MT; i++) { rowacc[i][0] = 0.f; rowacc[i][1] = 0.f; }

    const int arow = (l & 15);
    const int akof = (l >> 4) * 8;
    const int brow = ((l >> 4) & 1) * 8 + (l & 7);
    const int bkof = ((l >> 3) & 1) * 8;

    auto load_tiles = [&](int buf, int kc) {
        const uint32_t tb = base + (uint32_t)buf * BUFB;
        const size_t ak = (size_t)kc * BK_;
#pragma unroll
        for (int it = 0; it < AI; it++) {
            int idx = t + it * 256;
            int r = idx >> 3;
            int c = idx & 7;
            uint32_t sw = SW128((uint32_t)(r * 128 + c * 16));
            size_t aoff = (size_t)(m0 + r) * D_ + ak + c * 8;
            CP16(tb + sw, Ahi + aoff);
            if (PASSES == 3) CP16(tb + A_T + sw, Alo + aoff);
        }
#pragma unroll
        for (int it = 0; it < BI; it++) {
            int idx = t + it * 256;
            int r = idx >> 3;
            int c = idx & 7;
            uint32_t sw = SW128((uint32_t)(r * 128 + c * 16));
            size_t boff = (size_t)(nt * BNp + r) * D_ + ak + c * 8;
            CP16(tb + BH_O + sw, g_W1thi + boff);
            if (PASSES == 3) CP16(tb + BL_O + sw, g_W1tlo + boff);
        }
    };

    float acc[MT][JT][4];
#pragma unroll
    for (int i = 0; i < MT; i++)
#pragma unroll
        for (int j = 0; j < JT; j++)
#pragma unroll
            for (int q = 0; q < 4; q++) acc[i][j][q] = 0.f;

    load_tiles(0, 0);
    CP_COMMIT();

    for (int kc = 0; kc < NKC; kc++) {
        if (kc < NKC - 1) {
            load_tiles((kc + 1) & 1, kc + 1);
            CP_COMMIT();
            CP_WAIT1();
        } else {
            CP_WAIT0();
        }
        __syncthreads();

        const uint32_t tb = base + (uint32_t)(kc & 1) * BUFB;
#pragma unroll
        for (int s = 0; s < 4; s++) {
            uint32_t ah[MT][4], al[MT][4], bh[JT][2], bl[JT][2];
#pragma unroll
            for (int i = 0; i < MT; i++) {
                uint32_t r_ = (uint32_t)(wm * (MT * 16) + i * 16 + arow);
                uint32_t sw = SW128(r_ * 128 + (uint32_t)(s * 16 + akof) * 2);
                ldsm_x4(ah[i][0], ah[i][1], ah[i][2], ah[i][3], tb + sw);
                if (PASSES == 3)
                    ldsm_x4(al[i][0], al[i][1], al[i][2], al[i][3],
                            tb + A_T + sw);
            }
#pragma unroll
            for (int jj = 0; jj < JT; jj += 2) {
                uint32_t r_ = (uint32_t)(wn * (JT * 8) + jj * 8 + brow);
                uint32_t sw = SW128(r_ * 128 + (uint32_t)(s * 16 + bkof) * 2);
                ldsm_x4(bh[jj][0], bh[jj][1], bh[jj + 1][0], bh[jj + 1][1],
                        tb + BH_O + sw);
                if (PASSES == 3)
                    ldsm_x4(bl[jj][0], bl[jj][1], bl[jj + 1][0], bl[jj + 1][1],
                            tb + BL_O + sw);
            }
#pragma unroll
            for (int i = 0; i < MT; i++)
#pragma unroll
                for (int j = 0; j < JT; j++) {
                    mma_bf16(acc[i][j], ah[i], bh[j]);
                    if (PASSES == 3) {
                        mma_bf16(acc[i][j], ah[i], bl[j]);
                        mma_bf16(acc[i][j], al[i], bh[j]);
                    }
                }
        }
        __syncthreads();
    }

    // fused epilogue: relu(h + b1)·W2 per m-row
#pragma unroll
    for (int j = 0; j < JT; j++) {
        int n = nt * BNp + wn * (JT * 8) + j * 8 + (l & 3) * 2;
        float b1a = __ldg(&b1[n]), b1b = __ldg(&b1[n + 1]);
        float w2a = __ldg(&W2[n]), w2b = __ldg(&W2[n + 1]);
#pragma unroll
        for (int i = 0; i < MT; i++) {
            rowacc[i][0] += fmaxf(acc[i][j][0] + b1a, 0.f) * w2a
                          + fmaxf(acc[i][j][1] + b1b, 0.f) * w2b;
            rowacc[i][1] += fmaxf(acc[i][j][2] + b1a, 0.f) * w2a
                          + fmaxf(acc[i][j][3] + b1b, 0.f) * w2b;
        }
    }

    // reduce across (l&3) lanes, then across the 4 n-warps via smem
#pragma unroll
    for (int i = 0; i < MT; i++)
#pragma unroll
        for (int p = 0; p < 2; p++) {
            float v = rowacc[i][p];
            v += __shfl_xor_sync(0xffffffffu, v, 1);
            v += __shfl_xor_sync(0xffffffffu, v, 2);
            if ((l & 3) == 0)
                red[wm * (MT * 16) + i * 16 + (l >> 2) + p * 8][wn] = v;
        }
    __syncthreads();
    if (t < BMp)
        atomicAdd(&outp[m0 + t],
                  red[t][0] + red[t][1] + red[t][2] + red[t][3]);
}

// ------------------------- kernel: radix-select topk + collect --------------
__global__ void topk_collect_kernel() {
    __shared__ float s[S_];
    __shared__ int hist[256];
    __shared__ int sel_bin, rem_s;
    __shared__ float cutsh;
    __shared__ int scnt;
    const int row = blockIdx.x;
    const int t = threadIdx.x;
    const uint32_t rk0 = g_rng2k[0], rk1 = g_rng2k[1];
    for (int i = t; i < S_; i += blockDim.x) {
        int gi = row * S_ + i;
        s[i] = g_pert[gi] + jax_gumbel(rk0, rk1, (uint32_t)gi, (uint32_t)M_);
        g_sel[gi] = 0;
    }
    __syncthreads();

    uint32_t prefix = 0;
    int remaining = g_ksel;
#pragma unroll
    for (int level = 0; level < 4; level++) {
        const int shift = 24 - 8 * level;
        if (t < 256) hist[t] = 0;
        __syncthreads();
        for (int i = t; i < S_; i += blockDim.x) {
            uint32_t b = __float_as_uint(s[i]);
            uint32_t u = b ^ ((b & 0x80000000u) ? 0xFFFFFFFFu : 0x80000000u);
            bool ok = (level == 0) || ((u >> (shift + 8)) == prefix);
            if (ok) atomicAdd(&hist[(u >> shift) & 0xFFu], 1);
        }
        __syncthreads();
        if (t == 0) {
            int cum = 0, b = 255;
            for (; b > 0; b--) {
                int c = hist[b];
                if (cum + c >= remaining) break;
                cum += c;
            }
            sel_bin = b;
            rem_s = remaining - cum;
        }
        __syncthreads();
        prefix = (prefix << 8) | (uint32_t)sel_bin;
        remaining = rem_s;
        __syncthreads();
    }
    if (t == 0) {
        uint32_t u = prefix;
        uint32_t b = (u & 0x80000000u) ? (u ^ 0x80000000u) : (u ^ 0xFFFFFFFFu);
        cutsh = __uint_as_float(b) - DELTA;
        scnt = 0;
    }
    __syncthreads();
    for (int i = t; i < S_; i += blockDim.x) {
        if (s[i] >= cutsh) {
            int pos = atomicAdd(&scnt, 1);
            if (pos < CMAX) g_cand_idx[row * CMAX + pos] = row * S_ + i;
        }
    }
    __syncthreads();
    if (t == 0) g_cand_cnt[row] = (scnt < CMAX) ? scnt : CMAX;
}

// ------------------------- kernel: gather + split candidate rows ------------
__global__ void gather_kernel(const float* __restrict__ X) {
    int r = blockIdx.x / CMAX;
    int c = blockIdx.x % CMAX;
    if (threadIdx.x == 0) g_cand_logit[r * CMAX + c] = 0.f;  // refine accumulator
    if (c >= g_cand_cnt[r]) return;
    int tok = g_cand_idx[r * CMAX + c];
    const float* src = X + (size_t)tok * D_;
    __nv_bfloat16* dh = g_Chi + (size_t)(r * CMAX + c) * D_;
    __nv_bfloat16* dl = g_Clo + (size_t)(r * CMAX + c) * D_;
    int i0 = threadIdx.x * 8;   // 128 threads x 8
#pragma unroll
    for (int e = 0; e < 8; e += 4) {
        float4 v = *(const float4*)(src + i0 + e);
        __nv_bfloat16 h0 = __float2bfloat16(v.x), h1 = __float2bfloat16(v.y);
        __nv_bfloat16 h2 = __float2bfloat16(v.z), h3 = __float2bfloat16(v.w);
        __nv_bfloat16 l0 = __float2bfloat16(v.x - __bfloat162float(h0));
        __nv_bfloat16 l1 = __float2bfloat16(v.y - __bfloat162float(h1));
        __nv_bfloat16 l2 = __float2bfloat16(v.z - __bfloat162float(h2));
        __nv_bfloat16 l3 = __float2bfloat16(v.w - __bfloat162float(h3));
        __nv_bfloat162 hp0 = {h0, h1}, hp1 = {h2, h3};
        __nv_bfloat162 lp0 = {l0, l1}, lp1 = {l2, l3};
        *(uint2*)(dh + i0 + e) = make_uint2(*(uint32_t*)&hp0, *(uint32_t*)&hp1);
        *(uint2*)(dl + i0 + e) = make_uint2(*(uint32_t*)&lp0, *(uint32_t*)&lp1);
    }
}

// ------------------------- kernel: final exact top-k ------------------------
__global__ void final_select_kernel() {
    __shared__ float v[CMAX];
    int r = blockIdx.x;
    int t = threadIdx.x;
    int cnt = g_cand_cnt[r];
    int tok = -1;
    float val = -1e30f;
    if (t < cnt) {
        tok = g_cand_idx[r * CMAX + t];
        val = g_cand_logit[r * CMAX + t]
            + jax_gumbel(g_rng2k[0], g_rng2k[1], (uint32_t)tok, (uint32_t)M_);
    }
    v[t] = val;
    __syncthreads();
    for (int k = 2; k <= CMAX; k <<= 1) {
        for (int j = k >> 1; j > 0; j >>= 1) {
            int ixj = t ^ j;
            if (ixj > t) {
                bool up = ((t & k) == 0);
                float a = v[t], b = v[ixj];
                if ((a > b) == up) { v[t] = b; v[ixj] = a; }
            }
            __syncthreads();
        }
    }
    float th = v[CMAX - g_ksel];   // k-th largest
    __syncthreads();
    if (t < cnt && val >= th) g_sel[tok] = 1;
}

// ------------------------- kernel: copy selected rows + mask ----------------
__global__ void copy_out_kernel(const float* __restrict__ X,
                                float* __restrict__ out) {
    int r = blockIdx.x / CMAX;
    int c = blockIdx.x % CMAX;
    if (c >= g_cand_cnt[r]) return;
    int tok = g_cand_idx[r * CMAX + c];
    if (!g_sel[tok]) return;
    float4* dst = (float4*)(out + (size_t)tok * D_);
    const float4* src = (const float4*)(X + (size_t)tok * D_);
    dst[threadIdx.x] = src[threadIdx.x];
    if (threadIdx.x == 0) out[OUT_MASK_OFF + tok] = 1.0f;
}

// ============================================================================
extern "C" void kernel_launch(void* const* d_in, const int* in_sizes, int n_in,
                              void* d_out, int out_size) {
    const float* X        = (const float*)d_in[0];
    const float* W1       = (const float*)d_in[1];
    const float* b1       = (const float*)d_in[2];
    const float* W2       = (const float*)d_in[3];
    const float* k_logits = (const float*)d_in[5];
    float* out = (float*)d_out;

    auto* gemm_main   = gemm_kernel<1, 128, 256, 1>;  // grid (256, 8), 64x64 warp
    auto* gemm_refine = gemm_kernel<3, 64, 128, 2>;   // grid (16, 16)

    static void *p_xhi = nullptr, *p_chi, *p_clo, *p_pert, *p_clog;
    static cudaStream_t s2 = nullptr;
    static cudaEvent_t evFork, evW, evZ;
    if (!p_xhi) {
        cudaGetSymbolAddress(&p_xhi,  g_Xhi);
        cudaGetSymbolAddress(&p_chi,  g_Chi);
        cudaGetSymbolAddress(&p_clo,  g_Clo);
        cudaGetSymbolAddress(&p_pert, g_pert);
        cudaGetSymbolAddress(&p_clog, g_cand_logit);
        cudaFuncSetAttribute(gemm_main,
                             cudaFuncAttributeMaxDynamicSharedMemorySize, SMEM_GEMM);
        cudaFuncSetAttribute(gemm_refine,
                             cudaFuncAttributeMaxDynamicSharedMemorySize, SMEM_GEMM);
        cudaStreamCreateWithFlags(&s2, cudaStreamNonBlocking);
        cudaEventCreateWithFlags(&evFork, cudaEventDisableTiming);
        cudaEventCreateWithFlags(&evW,    cudaEventDisableTiming);
        cudaEventCreateWithFlags(&evZ,    cudaEventDisableTiming);
    }

    // ---- fork side stream: W1 prep + k-select + output zeroing -------------
    cudaEventRecord(evFork, 0);
    cudaStreamWaitEvent(s2, evFork, 0);
    convert_w1_kernel<<<dim3(H_ / 32, D_ / 32), 256, 0, s2>>>(W1);
    k_select_kernel<<<1, 64, 0, s2>>>(k_logits, out + OUT_EK_OFF);
    cudaEventRecord(evW, s2);
    zero_out_kernel<<<32800, 256, 0, s2>>>(out);   // runs under the GEMM
    cudaEventRecord(evZ, s2);

    // ---- main stream --------------------------------------------------------
    convert_x_kernel<<<(M_ * D_ / 4) / 256, 256>>>(X);
    cudaStreamWaitEvent(0, evW, 0);                 // need W1t + rng2k + ksel
    gemm_main<<<dim3(M_ / 128, H_ / 256), 256, SMEM_GEMM>>>(
        (const __nv_bfloat16*)p_xhi, nullptr, b1, W2, (float*)p_pert);
    topk_collect_kernel<<<B_, 1024>>>();
    gather_kernel<<<CTOT, 128>>>(X);
    gemm_refine<<<dim3(CTOT / 64, H_ / 128), 256, SMEM_GEMM>>>(
        (const __nv_bfloat16*)p_chi, (const __nv_bfloat16*)p_clo,
        b1, W2, (float*)p_clog);
    final_select_kernel<<<B_, CMAX>>>();
    cudaStreamWaitEvent(0, evZ, 0);                 // zeros in place
    copy_out_kernel<<<B_ * CMAX, 256>>>(X, out);
}

// round 12
// speedup vs baseline: 1.0139x; 1.0139x over previous
#include <cuda_runtime.h>
#include <cuda_bf16.h>
#include <cstdint>

// ============================================================================
// AdaptiveTokenFilter — GB300 sm_103a — 1-pass bf16 HMMA + exact 3-pass refine
// R12: revert GEMM to R10 shape (64x32 warp tile, 2 CTA/SM);
//      merge gather into topk_collect; merge final_select into copy_out.
// ============================================================================

#define B_ 8
#define S_ 4096
#define D_ 1024
#define H_ 2048
#define M_ (B_ * S_)            // 32768 tokens
#define MAXK 64
#define CMAX 128                // max candidates per row
#define CTOT (B_ * CMAX)        // 1024 compact rows
#define DELTA 0.1f              // candidate window (>=8x max 1-pass error)

#define OUT_MASK_OFF ((size_t)M_ * D_)
#define OUT_EK_OFF   ((size_t)M_ * D_ + M_)

#define THREEFRY_PARTITIONABLE 1

// GEMM tiling
#define BN_ 128
#define BK_ 64
#define NNT (H_ / BN_)          // 16 n-tiles
#define NKC (D_ / BK_)          // 16 k-chunks
#define NSPLIT 8                // main GEMM n-split

// dynamic smem per instantiation (2 stages + 1KB align slack)
#define SMEM_MAIN (2 * (128 * 128 + 16384) + 1024)          // 66560
#define SMEM_REF  (2 * (2 * 64 * 128 + 2 * 16384) + 1024)   // 99328

#define SW128(bo) ((bo) ^ (((bo) >> 3) & 0x70))

// ------------------------- device scratch (no allocs) -----------------------
__device__ __nv_bfloat16 g_Xhi[(size_t)M_ * D_];
__device__ __nv_bfloat16 g_W1thi[(size_t)H_ * D_];
__device__ __nv_bfloat16 g_W1tlo[(size_t)H_ * D_];
__device__ __nv_bfloat16 g_Chi[(size_t)CTOT * D_];
__device__ __nv_bfloat16 g_Clo[(size_t)CTOT * D_];
__device__ float    g_pert[M_];            // main: logit partials (atomic)
__device__ float    g_cand_logit[CTOT];
__device__ int      g_cand_idx[CTOT];      // global token ids
__device__ int      g_cand_cnt[B_];
__device__ int      g_ksel;
__device__ uint32_t g_rng2k[2];

// ------------------------- PTX helpers --------------------------------------
__device__ __forceinline__ uint32_t smem_u32(const void* p) {
    uint32_t a;
    asm("{ .reg .u64 t; cvta.to.shared.u64 t, %1; cvt.u32.u64 %0, t; }" : "=r"(a) : "l"(p));
    return a;
}
#define CP16(dst, src) \
    asm volatile("cp.async.cg.shared.global [%0], [%1], 16;" \
        :: "r"((uint32_t)(dst)), "l"((const void*)(src)) : "memory")
#define CP_COMMIT() asm volatile("cp.async.commit_group;" ::: "memory")
#define CP_WAIT1()  asm volatile("cp.async.wait_group 1;" ::: "memory")
#define CP_WAIT0()  asm volatile("cp.async.wait_group 0;" ::: "memory")

__device__ __forceinline__ void ldsm_x4(uint32_t& r0, uint32_t& r1,
                                        uint32_t& r2, uint32_t& r3, uint32_t a) {
    asm volatile("ldmatrix.sync.aligned.m8n8.x4.shared.b16 {%0,%1,%2,%3}, [%4];"
                 : "=r"(r0), "=r"(r1), "=r"(r2), "=r"(r3) : "r"(a));
}
__device__ __forceinline__ void mma_bf16(float* c, const uint32_t* a, const uint32_t* b) {
    asm volatile("mma.sync.aligned.m16n8k16.row.col.f32.bf16.bf16.f32 "
                 "{%0,%1,%2,%3}, {%4,%5,%6,%7}, {%8,%9}, {%0,%1,%2,%3};"
                 : "+f"(c[0]), "+f"(c[1]), "+f"(c[2]), "+f"(c[3])
                 : "r"(a[0]), "r"(a[1]), "r"(a[2]), "r"(a[3]), "r"(b[0]), "r"(b[1]));
}

// ------------------------- threefry2x32 (JAX-exact, 20 rounds) --------------
__device__ __forceinline__ uint32_t rotl32(uint32_t v, int r) {
    return (v << r) | (v >> (32 - r));
}
__device__ __forceinline__ void tf_rounds_a(uint32_t& x0, uint32_t& x1) {
    x0 += x1; x1 = rotl32(x1, 13); x1 ^= x0;
    x0 += x1; x1 = rotl32(x1, 15); x1 ^= x0;
    x0 += x1; x1 = rotl32(x1, 26); x1 ^= x0;
    x0 += x1; x1 = rotl32(x1,  6); x1 ^= x0;
}
__device__ __forceinline__ void tf_rounds_b(uint32_t& x0, uint32_t& x1) {
    x0 += x1; x1 = rotl32(x1, 17); x1 ^= x0;
    x0 += x1; x1 = rotl32(x1, 29); x1 ^= x0;
    x0 += x1; x1 = rotl32(x1, 16); x1 ^= x0;
    x0 += x1; x1 = rotl32(x1, 24); x1 ^= x0;
}
__device__ __forceinline__ void threefry2x32(uint32_t k1, uint32_t k2,
                                             uint32_t x0, uint32_t x1,
                                             uint32_t* o0, uint32_t* o1) {
    uint32_t ks2 = k1 ^ k2 ^ 0x1BD11BDAu;
    x0 += k1; x1 += k2;
    tf_rounds_a(x0, x1); x0 += k2;  x1 += ks2 + 1u;
    tf_rounds_b(x0, x1); x0 += ks2; x1 += k1  + 2u;
    tf_rounds_a(x0, x1); x0 += k1;  x1 += k2  + 3u;
    tf_rounds_b(x0, x1); x0 += k2;  x1 += ks2 + 4u;
    tf_rounds_a(x0, x1); x0 += ks2; x1 += k1  + 5u;
    *o0 = x0; *o1 = x1;
}
__device__ __forceinline__ uint32_t jax_random_bits32(uint32_t k1, uint32_t k2,
                                                      uint32_t idx, uint32_t n) {
#if THREEFRY_PARTITIONABLE
    uint32_t o0, o1;
    threefry2x32(k1, k2, 0u, idx, &o0, &o1);
    return o0 ^ o1;
#else
    uint32_t half = n >> 1;
    uint32_t o0, o1;
    if (idx < half) { threefry2x32(k1, k2, idx, idx + half, &o0, &o1); return o0; }
    else            { threefry2x32(k1, k2, idx - half, idx, &o0, &o1); return o1; }
#endif
}
__device__ __forceinline__ float jax_gumbel(uint32_t k1, uint32_t k2,
                                            uint32_t idx, uint32_t n) {
    uint32_t bits = jax_random_bits32(k1, k2, idx, n);
    float f = __uint_as_float((bits >> 9) | 0x3f800000u) - 1.0f;
    const float minv = 1e-8f;
    float u = __fadd_rn(__fmul_rn(f, 1.0f - 1e-8f), minv);
    u = fmaxf(minv, u);
    return -logf(-logf(u));
}

// ------------------------- kernel: X -> bf16 hi (+ zero pert) ---------------
__global__ void convert_x_kernel(const float* __restrict__ X) {
    if (threadIdx.x == 0) g_pert[blockIdx.x] = 0.f;   // 1 block == 1 token row
    size_t i = ((size_t)blockIdx.x * blockDim.x + threadIdx.x) * 4;
    float4 v = *(const float4*)(X + i);
    __nv_bfloat162 hp0 = {__float2bfloat16(v.x), __float2bfloat16(v.y)};
    __nv_bfloat162 hp1 = {__float2bfloat16(v.z), __float2bfloat16(v.w)};
    *(uint2*)&g_Xhi[i] = make_uint2(*(uint32_t*)&hp0, *(uint32_t*)&hp1);
}

// ------------------------- kernel: tiled transpose+split W1 -----------------
__global__ void convert_w1_kernel(const float* __restrict__ W1) {
    __shared__ float tile[32][33];
    const int bn = blockIdx.x;            // H/32 = 64
    const int bk = blockIdx.y;            // D/32 = 32
    const int tx = threadIdx.x & 31;
    const int ty = threadIdx.x >> 5;      // 0..7
#pragma unroll
    for (int i = 0; i < 4; i++) {
        int k = bk * 32 + ty + i * 8;
        tile[ty + i * 8][tx] = W1[(size_t)k * H_ + bn * 32 + tx];
    }
    __syncthreads();
#pragma unroll
    for (int i = 0; i < 4; i++) {
        int n = bn * 32 + ty + i * 8;
        int k = bk * 32 + tx;
        float v = tile[tx][ty + i * 8];
        __nv_bfloat16 h = __float2bfloat16(v);
        __nv_bfloat16 l = __float2bfloat16(v - __bfloat162float(h));
        g_W1thi[(size_t)n * D_ + k] = h;
        g_W1tlo[(size_t)n * D_ + k] = l;
    }
}

// ------------------------- kernel: k-selection path -------------------------
__global__ void k_select_kernel(const float* __restrict__ k_logits,
                                float* __restrict__ out_ek) {
    __shared__ float vals[MAXK];
    __shared__ uint32_t rngs[4];
    if (threadIdx.x == 0) {
        uint32_t a, b;
#if THREEFRY_PARTITIONABLE
        threefry2x32(0u, 42u, 0u, 0u, &a, &b); rngs[0] = a; rngs[1] = b;
        threefry2x32(0u, 42u, 0u, 1u, &a, &b); rngs[2] = a; rngs[3] = b;
#else
        uint32_t a0, b0, a1, b1;
        threefry2x32(0u, 42u, 0u, 2u, &a0, &b0);
        threefry2x32(0u, 42u, 1u, 3u, &a1, &b1);
        rngs[0] = a0; rngs[1] = a1; rngs[2] = b0; rngs[3] = b1;
#endif
        g_rng2k[0] = rngs[2]; g_rng2k[1] = rngs[3];
    }
    __syncthreads();
    int i = threadIdx.x;
    float g = jax_gumbel(rngs[0], rngs[1], (uint32_t)i, MAXK);
    vals[i] = k_logits[i] + g;
    __syncthreads();
    if (i == 0) {
        float mx = vals[0]; int am = 0;
        for (int j = 1; j < MAXK; j++)
            if (vals[j] > mx) { mx = vals[j]; am = j; }
        float sum = 0.f, ek = 0.f;
        for (int j = 0; j < MAXK; j++) {
            float e = expf(vals[j] - mx);
            sum += e; ek += e * (float)(j + 1);
        }
        g_ksel = am + 1;
        out_ek[0] = ek / sum;
    }
}

// ------------------------- kernel: zero output (emb + mask) -----------------
// 33587200 floats = 32800 blocks x 256 threads x float4 exactly; ek excluded.
__global__ void zero_out_kernel(float* __restrict__ out) {
    size_t i = ((size_t)blockIdx.x * 256 + threadIdx.x) * 4;
    *(float4*)(out + i) = make_float4(0.f, 0.f, 0.f, 0.f);
}

// ------------------------- templated HMMA GEMM (R10 2-stage core) -----------
// Accumulates relu(A·W1t + b1)·W2 over NT_CHUNK n-tiles (offset blockIdx.y),
// atomicAdd partial per m-row into outp. BMp = CTA tile height (128 or 64).
template<int PASSES, int BMp, int NT_CHUNK, int MINB>
__global__ void __launch_bounds__(256, MINB)
gemm_kernel(const __nv_bfloat16* __restrict__ Ahi,
            const __nv_bfloat16* __restrict__ Alo,
            const float* __restrict__ b1,
            const float* __restrict__ W2,
            float* __restrict__ outp) {
    extern __shared__ char dyn_smem[];
    __shared__ float red[BMp][4];

    constexpr int MT = BMp / 32;                     // i-tiles per warp
    constexpr uint32_t A_T  = (uint32_t)BMp * 128;   // one A tile bytes
    constexpr uint32_t BH_O = (PASSES == 3) ? 2 * A_T : A_T;
    constexpr uint32_t BL_O = BH_O + 16384;
    constexpr uint32_t BUFB = BH_O + ((PASSES == 3) ? 2 : 1) * 16384;
    constexpr int AI = BMp * 8 / 256;                // A loader iterations

    const uint32_t braw = smem_u32(dyn_smem);
    const uint32_t base = (braw + 1023u) & ~1023u;

    const int t   = threadIdx.x;
    const int l   = t & 31;
    const int wid = t >> 5;
    const int wm  = wid >> 2;      // 0..1
    const int wn  = wid & 3;       // 0..3
    const int m0  = blockIdx.x * BMp;

    float rowacc[MT][2];
#pragma unroll
    for (int i = 0; i < MT; i++) { rowacc[i][0] = 0.f; rowacc[i][1] = 0.f; }

    const int arow = (l & 15);
    const int akof = (l >> 4) * 8;
    const int brow = ((l >> 4) & 1) * 8 + (l & 7);
    const int bkof = ((l >> 3) & 1) * 8;

    auto load_tiles = [&](int buf, int nt, int kc) {
        const uint32_t tb = base + (uint32_t)buf * BUFB;
        const size_t ak = (size_t)kc * BK_;
#pragma unroll
        for (int it = 0; it < AI; it++) {
            int idx = t + it * 256;
            int r = idx >> 3;
            int c = idx & 7;
            uint32_t sw = SW128((uint32_t)(r * 128 + c * 16));
            size_t aoff = (size_t)(m0 + r) * D_ + ak + c * 8;
            CP16(tb + sw, Ahi + aoff);
            if (PASSES == 3) CP16(tb + A_T + sw, Alo + aoff);
        }
#pragma unroll
        for (int it = 0; it < 4; it++) {
            int idx = t + it * 256;
            int r = idx >> 3;
            int c = idx & 7;
            uint32_t sw = SW128((uint32_t)(r * 128 + c * 16));
            size_t boff = (size_t)(nt * BN_ + r) * D_ + ak + c * 8;
            CP16(tb + BH_O + sw, g_W1thi + boff);
            if (PASSES == 3) CP16(tb + BL_O + sw, g_W1tlo + boff);
        }
    };

    for (int nti = 0; nti < NT_CHUNK; nti++) {
        const int nt = blockIdx.y * NT_CHUNK + nti;
        float acc[MT][4][4];
#pragma unroll
        for (int i = 0; i < MT; i++)
#pragma unroll
            for (int j = 0; j < 4; j++)
#pragma unroll
                for (int q = 0; q < 4; q++) acc[i][j][q] = 0.f;

        load_tiles(0, nt, 0);
        CP_COMMIT();

        for (int kc = 0; kc < NKC; kc++) {
            if (kc < NKC - 1) {
                load_tiles((kc + 1) & 1, nt, kc + 1);
                CP_COMMIT();
                CP_WAIT1();
            } else {
                CP_WAIT0();
            }
            __syncthreads();

            const uint32_t tb = base + (uint32_t)(kc & 1) * BUFB;
#pragma unroll
            for (int s = 0; s < 4; s++) {
                uint32_t ah[MT][4], al[MT][4], bh[4][2], bl[4][2];
#pragma unroll
                for (int i = 0; i < MT; i++) {
                    uint32_t r_ = (uint32_t)(wm * (MT * 16) + i * 16 + arow);
                    uint32_t sw = SW128(r_ * 128 + (uint32_t)(s * 16 + akof) * 2);
                    ldsm_x4(ah[i][0], ah[i][1], ah[i][2], ah[i][3], tb + sw);
                    if (PASSES == 3)
                        ldsm_x4(al[i][0], al[i][1], al[i][2], al[i][3],
                                tb + A_T + sw);
                }
#pragma unroll
                for (int jj = 0; jj < 4; jj += 2) {
                    uint32_t r_ = (uint32_t)(wn * 32 + jj * 8 + brow);
                    uint32_t sw = SW128(r_ * 128 + (uint32_t)(s * 16 + bkof) * 2);
                    ldsm_x4(bh[jj][0], bh[jj][1], bh[jj + 1][0], bh[jj + 1][1],
                            tb + BH_O + sw);
                    if (PASSES == 3)
                        ldsm_x4(bl[jj][0], bl[jj][1], bl[jj + 1][0], bl[jj + 1][1],
                                tb + BL_O + sw);
                }
#pragma unroll
                for (int i = 0; i < MT; i++)
#pragma unroll
                    for (int j = 0; j < 4; j++) {
                        mma_bf16(acc[i][j], ah[i], bh[j]);
                        if (PASSES == 3) {
                            mma_bf16(acc[i][j], ah[i], bl[j]);
                            mma_bf16(acc[i][j], al[i], bh[j]);
                        }
                    }
            }
            __syncthreads();
        }

        // fused epilogue: relu(h + b1)·W2 per m-row for this n-tile
#pragma unroll
        for (int j = 0; j < 4; j++) {
            int n = nt * BN_ + wn * 32 + j * 8 + (l & 3) * 2;
            float b1a = __ldg(&b1[n]), b1b = __ldg(&b1[n + 1]);
            float w2a = __ldg(&W2[n]), w2b = __ldg(&W2[n + 1]);
#pragma unroll
            for (int i = 0; i < MT; i++) {
                rowacc[i][0] += fmaxf(acc[i][j][0] + b1a, 0.f) * w2a
                              + fmaxf(acc[i][j][1] + b1b, 0.f) * w2b;
                rowacc[i][1] += fmaxf(acc[i][j][2] + b1a, 0.f) * w2a
                              + fmaxf(acc[i][j][3] + b1b, 0.f) * w2b;
            }
        }
    }

    // reduce across (l&3) lanes, then across the 4 n-warps via smem
#pragma unroll
    for (int i = 0; i < MT; i++)
#pragma unroll
        for (int p = 0; p < 2; p++) {
            float v = rowacc[i][p];
            v += __shfl_xor_sync(0xffffffffu, v, 1);
            v += __shfl_xor_sync(0xffffffffu, v, 2);
            if ((l & 3) == 0)
                red[wm * (MT * 16) + i * 16 + (l >> 2) + p * 8][wn] = v;
        }
    __syncthreads();
    if (t < BMp)
        atomicAdd(&outp[m0 + t],
                  red[t][0] + red[t][1] + red[t][2] + red[t][3]);
}

// ------------------------- kernel: topk + collect + gather (merged) ---------
// pert = logit + gumbel; exact k-th largest via 4x 8-bit radix passes;
// collects candidates >= kth - DELTA; then gathers+splits their X rows.
__global__ void topk_collect_gather_kernel(const float* __restrict__ X) {
    __shared__ float s[S_];
    __shared__ int hist[256];
    __shared__ int sel_bin, rem_s;
    __shared__ float cutsh;
    __shared__ int scnt;
    const int row = blockIdx.x;
    const int t = threadIdx.x;
    const uint32_t rk0 = g_rng2k[0], rk1 = g_rng2k[1];
    for (int i = t; i < S_; i += blockDim.x) {
        int gi = row * S_ + i;
        s[i] = g_pert[gi] + jax_gumbel(rk0, rk1, (uint32_t)gi, (uint32_t)M_);
    }
    if (t < CMAX) g_cand_logit[row * CMAX + t] = 0.f;   // refine accumulators
    __syncthreads();

    uint32_t prefix = 0;
    int remaining = g_ksel;
#pragma unroll
    for (int level = 0; level < 4; level++) {
        const int shift = 24 - 8 * level;
        if (t < 256) hist[t] = 0;
        __syncthreads();
        for (int i = t; i < S_; i += blockDim.x) {
            uint32_t b = __float_as_uint(s[i]);
            uint32_t u = b ^ ((b & 0x80000000u) ? 0xFFFFFFFFu : 0x80000000u);
            bool ok = (level == 0) || ((u >> (shift + 8)) == prefix);
            if (ok) atomicAdd(&hist[(u >> shift) & 0xFFu], 1);
        }
        __syncthreads();
        if (t == 0) {
            int cum = 0, b = 255;
            for (; b > 0; b--) {
                int c = hist[b];
                if (cum + c >= remaining) break;
                cum += c;
            }
            sel_bin = b;
            rem_s = remaining - cum;
        }
        __syncthreads();
        prefix = (prefix << 8) | (uint32_t)sel_bin;
        remaining = rem_s;
        __syncthreads();
    }
    if (t == 0) {
        uint32_t u = prefix;
        uint32_t b = (u & 0x80000000u) ? (u ^ 0x80000000u) : (u ^ 0xFFFFFFFFu);
        cutsh = __uint_as_float(b) - DELTA;
        scnt = 0;
    }
    __syncthreads();
    for (int i = t; i < S_; i += blockDim.x) {
        if (s[i] >= cutsh) {
            int pos = atomicAdd(&scnt, 1);
            if (pos < CMAX) g_cand_idx[row * CMAX + pos] = row * S_ + i;
        }
    }
    __syncthreads();
    const int cnt = (scnt < CMAX) ? scnt : CMAX;
    if (t == 0) g_cand_cnt[row] = cnt;

    // gather + bf16-split candidate rows (8 threads per row chunk of 128)
    for (int w = t; w < cnt * 128; w += blockDim.x) {
        int c  = w >> 7;           // candidate slot
        int e0 = (w & 127) * 8;    // 8 elems per work item
        int tok = g_cand_idx[row * CMAX + c];
        const float* src = X + (size_t)tok * D_ + e0;
        __nv_bfloat16* dh = g_Chi + (size_t)(row * CMAX + c) * D_ + e0;
        __nv_bfloat16* dl = g_Clo + (size_t)(row * CMAX + c) * D_ + e0;
#pragma unroll
        for (int e = 0; e < 8; e += 4) {
            float4 v = *(const float4*)(src + e);
            __nv_bfloat16 h0 = __float2bfloat16(v.x), h1 = __float2bfloat16(v.y);
            __nv_bfloat16 h2 = __float2bfloat16(v.z), h3 = __float2bfloat16(v.w);
            __nv_bfloat16 l0 = __float2bfloat16(v.x - __bfloat162float(h0));
            __nv_bfloat16 l1 = __float2bfloat16(v.y - __bfloat162float(h1));
            __nv_bfloat16 l2 = __float2bfloat16(v.z - __bfloat162float(h2));
            __nv_bfloat16 l3 = __float2bfloat16(v.w - __bfloat162float(h3));
            __nv_bfloat162 hp0 = {h0, h1}, hp1 = {h2, h3};
            __nv_bfloat162 lp0 = {l0, l1}, lp1 = {l2, l3};
            *(uint2*)(dh + e) = make_uint2(*(uint32_t*)&hp0, *(uint32_t*)&hp1);
            *(uint2*)(dl + e) = make_uint2(*(uint32_t*)&lp0, *(uint32_t*)&lp1);
        }
    }
    // zero smem of un-gathered candidate slots? not needed: refine computes
    // garbage logits for slots >= cnt; final selection ignores them (val=-inf).
}

// ------------------------- kernel: final select + copy (merged) -------------
// One block per batch row: bitonic over CMAX candidate perts -> threshold,
// then copies selected rows into the (pre-zeroed) output + writes mask.
__global__ void select_copy_kernel(const float* __restrict__ X,
                                   float* __restrict__ out) {
    __shared__ float v[CMAX];
    __shared__ float vs[CMAX];     // unsorted copy for membership test
    const int r = blockIdx.x;
    const int t = threadIdx.x;     // 256 threads
    const int cnt = g_cand_cnt[r];
    if (t < CMAX) {
        float val = -1e30f;
        if (t < cnt) {
            int tok = g_cand_idx[r * CMAX + t];
            val = g_cand_logit[r * CMAX + t]
                + jax_gumbel(g_rng2k[0], g_rng2k[1], (uint32_t)tok, (uint32_t)M_);
        }
        v[t] = val;
        vs[t] = val;
    }
    __syncthreads();
    for (int k = 2; k <= CMAX; k <<= 1) {
        for (int j = k >> 1; j > 0; j >>= 1) {
            if (t < CMAX) {
                int ixj = t ^ j;
                if (ixj > t) {
                    bool up = ((t & k) == 0);
                    float a = v[t], b = v[ixj];
                    if ((a > b) == up) { v[t] = b; v[ixj] = a; }
                }
            }
            __syncthreads();
        }
    }
    const float th = v[CMAX - g_ksel];   // k-th largest
    __syncthreads();
    // copy each selected candidate row (256 threads = one row of float4s)
    for (int c = 0; c < cnt; c++) {
        if (vs[c] >= th) {
            int tok = g_cand_idx[r * CMAX + c];
            float4* dst = (float4*)(out + (size_t)tok * D_);
            const float4* src = (const float4*)(X + (size_t)tok * D_);
            dst[threadIdx.x] = src[threadIdx.x];
            if (t == 0) out[OUT_MASK_OFF + tok] = 1.0f;
        }
    }
}

// ============================================================================
extern "C" void kernel_launch(void* const* d_in, const int* in_sizes, int n_in,
                              void* d_out, int out_size) {
    const float* X        = (const float*)d_in[0];
    const float* W1       = (const float*)d_in[1];
    const float* b1       = (const float*)d_in[2];
    const float* W2       = (const float*)d_in[3];
    const float* k_logits = (const float*)d_in[5];
    float* out = (float*)d_out;

    auto* gemm_main   = gemm_kernel<1, 128, 2, 2>;   // grid (256, 8)
    auto* gemm_refine = gemm_kernel<3, 64, 1, 2>;    // grid (16, 16)

    static void *p_xhi = nullptr, *p_chi, *p_clo, *p_pert, *p_clog;
    static cudaStream_t s2 = nullptr;
    static cudaEvent_t evFork, evW, evZ;
    if (!p_xhi) {
        cudaGetSymbolAddress(&p_xhi,  g_Xhi);
        cudaGetSymbolAddress(&p_chi,  g_Chi);
        cudaGetSymbolAddress(&p_clo,  g_Clo);
        cudaGetSymbolAddress(&p_pert, g_pert);
        cudaGetSymbolAddress(&p_clog, g_cand_logit);
        cudaFuncSetAttribute(gemm_main,
                             cudaFuncAttributeMaxDynamicSharedMemorySize, SMEM_MAIN);
        cudaFuncSetAttribute(gemm_refine,
                             cudaFuncAttributeMaxDynamicSharedMemorySize, SMEM_REF);
        cudaStreamCreateWithFlags(&s2, cudaStreamNonBlocking);
        cudaEventCreateWithFlags(&evFork, cudaEventDisableTiming);
        cudaEventCreateWithFlags(&evW,    cudaEventDisableTiming);
        cudaEventCreateWithFlags(&evZ,    cudaEventDisableTiming);
    }

    // ---- fork side stream: W1 prep + k-select + output zeroing -------------
    cudaEventRecord(evFork, 0);
    cudaStreamWaitEvent(s2, evFork, 0);
    convert_w1_kernel<<<dim3(H_ / 32, D_ / 32), 256, 0, s2>>>(W1);
    k_select_kernel<<<1, 64, 0, s2>>>(k_logits, out + OUT_EK_OFF);
    cudaEventRecord(evW, s2);
    zero_out_kernel<<<32800, 256, 0, s2>>>(out);   // runs under the GEMM
    cudaEventRecord(evZ, s2);

    // ---- main stream --------------------------------------------------------
    convert_x_kernel<<<(M_ * D_ / 4) / 256, 256>>>(X);
    cudaStreamWaitEvent(0, evW, 0);                 // need W1t + rng2k + ksel
    gemm_main<<<dim3(M_ / 128, NSPLIT), 256, SMEM_MAIN>>>(
        (const __nv_bfloat16*)p_xhi, nullptr, b1, W2, (float*)p_pert);
    topk_collect_gather_kernel<<<B_, 1024>>>(X);
    gemm_refine<<<dim3(CTOT / 64, NNT), 256, SMEM_REF>>>(
        (const __nv_bfloat16*)p_chi, (const __nv_bfloat16*)p_clo,
        b1, W2, (float*)p_clog);
    cudaStreamWaitEvent(0, evZ, 0);                 // zeros in place
    select_copy_kernel<<<B_, 256>>>(X, out);
}

// round 13
// speedup vs baseline: 1.0382x; 1.0240x over previous
#include <cuda_runtime.h>
#include <cuda_bf16.h>
#include <cstdint>

// ============================================================================
// AdaptiveTokenFilter — GB300 sm_103a — 1-pass bf16 HMMA + exact 3-pass refine
// R13: R10 skeleton; convert_x with 2x ILP; topk+gather merged (parallel-safe);
//      R10-style final_select + 1024-block copy_out restored.
// ============================================================================

#define B_ 8
#define S_ 4096
#define D_ 1024
#define H_ 2048
#define M_ (B_ * S_)            // 32768 tokens
#define MAXK 64
#define CMAX 128                // max candidates per row
#define CTOT (B_ * CMAX)        // 1024 compact rows
#define DELTA 0.1f              // candidate window (>=8x max 1-pass error)

#define OUT_MASK_OFF ((size_t)M_ * D_)
#define OUT_EK_OFF   ((size_t)M_ * D_ + M_)

#define THREEFRY_PARTITIONABLE 1

// GEMM tiling
#define BN_ 128
#define BK_ 64
#define NNT (H_ / BN_)          // 16 n-tiles
#define NKC (D_ / BK_)          // 16 k-chunks
#define NSPLIT 8                // main GEMM n-split

// dynamic smem per instantiation (2 stages + 1KB align slack)
#define SMEM_MAIN (2 * (128 * 128 + 16384) + 1024)          // 66560
#define SMEM_REF  (2 * (2 * 64 * 128 + 2 * 16384) + 1024)   // 99328

#define SW128(bo) ((bo) ^ (((bo) >> 3) & 0x70))

// ------------------------- device scratch (no allocs) -----------------------
__device__ __nv_bfloat16 g_Xhi[(size_t)M_ * D_];
__device__ __nv_bfloat16 g_W1thi[(size_t)H_ * D_];
__device__ __nv_bfloat16 g_W1tlo[(size_t)H_ * D_];
__device__ __nv_bfloat16 g_Chi[(size_t)CTOT * D_];
__device__ __nv_bfloat16 g_Clo[(size_t)CTOT * D_];
__device__ float    g_pert[M_];            // main: logit partials (atomic)
__device__ float    g_cand_logit[CTOT];
__device__ int      g_cand_idx[CTOT];      // global token ids
__device__ int      g_cand_cnt[B_];
__device__ unsigned char g_sel[M_];
__device__ int      g_ksel;
__device__ uint32_t g_rng2k[2];

// ------------------------- PTX helpers --------------------------------------
__device__ __forceinline__ uint32_t smem_u32(const void* p) {
    uint32_t a;
    asm("{ .reg .u64 t; cvta.to.shared.u64 t, %1; cvt.u32.u64 %0, t; }" : "=r"(a) : "l"(p));
    return a;
}
#define CP16(dst, src) \
    asm volatile("cp.async.cg.shared.global [%0], [%1], 16;" \
        :: "r"((uint32_t)(dst)), "l"((const void*)(src)) : "memory")
#define CP_COMMIT() asm volatile("cp.async.commit_group;" ::: "memory")
#define CP_WAIT1()  asm volatile("cp.async.wait_group 1;" ::: "memory")
#define CP_WAIT0()  asm volatile("cp.async.wait_group 0;" ::: "memory")

__device__ __forceinline__ void ldsm_x4(uint32_t& r0, uint32_t& r1,
                                        uint32_t& r2, uint32_t& r3, uint32_t a) {
    asm volatile("ldmatrix.sync.aligned.m8n8.x4.shared.b16 {%0,%1,%2,%3}, [%4];"
                 : "=r"(r0), "=r"(r1), "=r"(r2), "=r"(r3) : "r"(a));
}
__device__ __forceinline__ void mma_bf16(float* c, const uint32_t* a, const uint32_t* b) {
    asm volatile("mma.sync.aligned.m16n8k16.row.col.f32.bf16.bf16.f32 "
                 "{%0,%1,%2,%3}, {%4,%5,%6,%7}, {%8,%9}, {%0,%1,%2,%3};"
                 : "+f"(c[0]), "+f"(c[1]), "+f"(c[2]), "+f"(c[3])
                 : "r"(a[0]), "r"(a[1]), "r"(a[2]), "r"(a[3]), "r"(b[0]), "r"(b[1]));
}

// ------------------------- threefry2x32 (JAX-exact, 20 rounds) --------------
__device__ __forceinline__ uint32_t rotl32(uint32_t v, int r) {
    return (v << r) | (v >> (32 - r));
}
__device__ __forceinline__ void tf_rounds_a(uint32_t& x0, uint32_t& x1) {
    x0 += x1; x1 = rotl32(x1, 13); x1 ^= x0;
    x0 += x1; x1 = rotl32(x1, 15); x1 ^= x0;
    x0 += x1; x1 = rotl32(x1, 26); x1 ^= x0;
    x0 += x1; x1 = rotl32(x1,  6); x1 ^= x0;
}
__device__ __forceinline__ void tf_rounds_b(uint32_t& x0, uint32_t& x1) {
    x0 += x1; x1 = rotl32(x1, 17); x1 ^= x0;
    x0 += x1; x1 = rotl32(x1, 29); x1 ^= x0;
    x0 += x1; x1 = rotl32(x1, 16); x1 ^= x0;
    x0 += x1; x1 = rotl32(x1, 24); x1 ^= x0;
}
__device__ __forceinline__ void threefry2x32(uint32_t k1, uint32_t k2,
                                             uint32_t x0, uint32_t x1,
                                             uint32_t* o0, uint32_t* o1) {
    uint32_t ks2 = k1 ^ k2 ^ 0x1BD11BDAu;
    x0 += k1; x1 += k2;
    tf_rounds_a(x0, x1); x0 += k2;  x1 += ks2 + 1u;
    tf_rounds_b(x0, x1); x0 += ks2; x1 += k1  + 2u;
    tf_rounds_a(x0, x1); x0 += k1;  x1 += k2  + 3u;
    tf_rounds_b(x0, x1); x0 += k2;  x1 += ks2 + 4u;
    tf_rounds_a(x0, x1); x0 += ks2; x1 += k1  + 5u;
    *o0 = x0; *o1 = x1;
}
__device__ __forceinline__ uint32_t jax_random_bits32(uint32_t k1, uint32_t k2,
                                                      uint32_t idx, uint32_t n) {
#if THREEFRY_PARTITIONABLE
    uint32_t o0, o1;
    threefry2x32(k1, k2, 0u, idx, &o0, &o1);
    return o0 ^ o1;
#else
    uint32_t half = n >> 1;
    uint32_t o0, o1;
    if (idx < half) { threefry2x32(k1, k2, idx, idx + half, &o0, &o1); return o0; }
    else            { threefry2x32(k1, k2, idx - half, idx, &o0, &o1); return o1; }
#endif
}
__device__ __forceinline__ float jax_gumbel(uint32_t k1, uint32_t k2,
                                            uint32_t idx, uint32_t n) {
    uint32_t bits = jax_random_bits32(k1, k2, idx, n);
    float f = __uint_as_float((bits >> 9) | 0x3f800000u) - 1.0f;
    const float minv = 1e-8f;
    float u = __fadd_rn(__fmul_rn(f, 1.0f - 1e-8f), minv);
    u = fmaxf(minv, u);
    return -logf(-logf(u));
}

// ------------------------- kernel: X -> bf16 hi (+ zero pert), 2x ILP -------
__global__ void convert_x_kernel(const float* __restrict__ X) {
    if (threadIdx.x < 2) g_pert[blockIdx.x * 2 + threadIdx.x] = 0.f;
    size_t i = ((size_t)blockIdx.x * blockDim.x + threadIdx.x) * 8;
    float4 v0 = *(const float4*)(X + i);
    float4 v1 = *(const float4*)(X + i + 4);
    __nv_bfloat162 a0 = {__float2bfloat16(v0.x), __float2bfloat16(v0.y)};
    __nv_bfloat162 a1 = {__float2bfloat16(v0.z), __float2bfloat16(v0.w)};
    __nv_bfloat162 b0 = {__float2bfloat16(v1.x), __float2bfloat16(v1.y)};
    __nv_bfloat162 b1 = {__float2bfloat16(v1.z), __float2bfloat16(v1.w)};
    *(uint4*)&g_Xhi[i] = make_uint4(*(uint32_t*)&a0, *(uint32_t*)&a1,
                                    *(uint32_t*)&b0, *(uint32_t*)&b1);
}

// ------------------------- kernel: tiled transpose+split W1 -----------------
__global__ void convert_w1_kernel(const float* __restrict__ W1) {
    __shared__ float tile[32][33];
    const int bn = blockIdx.x;            // H/32 = 64
    const int bk = blockIdx.y;            // D/32 = 32
    const int tx = threadIdx.x & 31;
    const int ty = threadIdx.x >> 5;      // 0..7
#pragma unroll
    for (int i = 0; i < 4; i++) {
        int k = bk * 32 + ty + i * 8;
        tile[ty + i * 8][tx] = W1[(size_t)k * H_ + bn * 32 + tx];
    }
    __syncthreads();
#pragma unroll
    for (int i = 0; i < 4; i++) {
        int n = bn * 32 + ty + i * 8;
        int k = bk * 32 + tx;
        float v = tile[tx][ty + i * 8];
        __nv_bfloat16 h = __float2bfloat16(v);
        __nv_bfloat16 l = __float2bfloat16(v - __bfloat162float(h));
        g_W1thi[(size_t)n * D_ + k] = h;
        g_W1tlo[(size_t)n * D_ + k] = l;
    }
}

// ------------------------- kernel: k-selection path -------------------------
__global__ void k_select_kernel(const float* __restrict__ k_logits,
                                float* __restrict__ out_ek) {
    __shared__ float vals[MAXK];
    __shared__ uint32_t rngs[4];
    if (threadIdx.x == 0) {
        uint32_t a, b;
#if THREEFRY_PARTITIONABLE
        threefry2x32(0u, 42u, 0u, 0u, &a, &b); rngs[0] = a; rngs[1] = b;
        threefry2x32(0u, 42u, 0u, 1u, &a, &b); rngs[2] = a; rngs[3] = b;
#else
        uint32_t a0, b0, a1, b1;
        threefry2x32(0u, 42u, 0u, 2u, &a0, &b0);
        threefry2x32(0u, 42u, 1u, 3u, &a1, &b1);
        rngs[0] = a0; rngs[1] = a1; rngs[2] = b0; rngs[3] = b1;
#endif
        g_rng2k[0] = rngs[2]; g_rng2k[1] = rngs[3];
    }
    __syncthreads();
    int i = threadIdx.x;
    float g = jax_gumbel(rngs[0], rngs[1], (uint32_t)i, MAXK);
    vals[i] = k_logits[i] + g;
    __syncthreads();
    if (i == 0) {
        float mx = vals[0]; int am = 0;
        for (int j = 1; j < MAXK; j++)
            if (vals[j] > mx) { mx = vals[j]; am = j; }
        float sum = 0.f, ek = 0.f;
        for (int j = 0; j < MAXK; j++) {
            float e = expf(vals[j] - mx);
            sum += e; ek += e * (float)(j + 1);
        }
        g_ksel = am + 1;
        out_ek[0] = ek / sum;
    }
}

// ------------------------- kernel: zero output (emb + mask) -----------------
__global__ void zero_out_kernel(float* __restrict__ out) {
    size_t i = ((size_t)blockIdx.x * 256 + threadIdx.x) * 4;
    *(float4*)(out + i) = make_float4(0.f, 0.f, 0.f, 0.f);
}

// ------------------------- templated HMMA GEMM (R10 2-stage core) -----------
template<int PASSES, int BMp, int NT_CHUNK, int MINB>
__global__ void __launch_bounds__(256, MINB)
gemm_kernel(const __nv_bfloat16* __restrict__ Ahi,
            const __nv_bfloat16* __restrict__ Alo,
            const float* __restrict__ b1,
            const float* __restrict__ W2,
            float* __restrict__ outp) {
    extern __shared__ char dyn_smem[];
    __shared__ float red[BMp][4];

    constexpr int MT = BMp / 32;
    constexpr uint32_t A_T  = (uint32_t)BMp * 128;
    constexpr uint32_t BH_O = (PASSES == 3) ? 2 * A_T : A_T;
    constexpr uint32_t BL_O = BH_O + 16384;
    constexpr uint32_t BUFB = BH_O + ((PASSES == 3) ? 2 : 1) * 16384;
    constexpr int AI = BMp * 8 / 256;

    const uint32_t braw = smem_u32(dyn_smem);
    const uint32_t base = (braw + 1023u) & ~1023u;

    const int t   = threadIdx.x;
    const int l   = t & 31;
    const int wid = t >> 5;
    const int wm  = wid >> 2;
    const int wn  = wid & 3;
    const int m0  = blockIdx.x * BMp;

    float rowacc[MT][2];
#pragma unroll
    for (int i = 0; i < MT; i++) { rowacc[i][0] = 0.f; rowacc[i][1] = 0.f; }

    const int arow = (l & 15);
    const int akof = (l >> 4) * 8;
    const int brow = ((l >> 4) & 1) * 8 + (l & 7);
    const int bkof = ((l >> 3) & 1) * 8;

    auto load_tiles = [&](int buf, int nt, int kc) {
        const uint32_t tb = base + (uint32_t)buf * BUFB;
        const size_t ak = (size_t)kc * BK_;
#pragma unroll
        for (int it = 0; it < AI; it++) {
            int idx = t + it * 256;
            int r = idx >> 3;
            int c = idx & 7;
            uint32_t sw = SW128((uint32_t)(r * 128 + c * 16));
            size_t aoff = (size_t)(m0 + r) * D_ + ak + c * 8;
            CP16(tb + sw, Ahi + aoff);
            if (PASSES == 3) CP16(tb + A_T + sw, Alo + aoff);
        }
#pragma unroll
        for (int it = 0; it < 4; it++) {
            int idx = t + it * 256;
            int r = idx >> 3;
            int c = idx & 7;
            uint32_t sw = SW128((uint32_t)(r * 128 + c * 16));
            size_t boff = (size_t)(nt * BN_ + r) * D_ + ak + c * 8;
            CP16(tb + BH_O + sw, g_W1thi + boff);
            if (PASSES == 3) CP16(tb + BL_O + sw, g_W1tlo + boff);
        }
    };

    for (int nti = 0; nti < NT_CHUNK; nti++) {
        const int nt = blockIdx.y * NT_CHUNK + nti;
        float acc[MT][4][4];
#pragma unroll
        for (int i = 0; i < MT; i++)
#pragma unroll
            for (int j = 0; j < 4; j++)
#pragma unroll
                for (int q = 0; q < 4; q++) acc[i][j][q] = 0.f;

        load_tiles(0, nt, 0);
        CP_COMMIT();

        for (int kc = 0; kc < NKC; kc++) {
            if (kc < NKC - 1) {
                load_tiles((kc + 1) & 1, nt, kc + 1);
                CP_COMMIT();
                CP_WAIT1();
            } else {
                CP_WAIT0();
            }
            __syncthreads();

            const uint32_t tb = base + (uint32_t)(kc & 1) * BUFB;
#pragma unroll
            for (int s = 0; s < 4; s++) {
                uint32_t ah[MT][4], al[MT][4], bh[4][2], bl[4][2];
#pragma unroll
                for (int i = 0; i < MT; i++) {
                    uint32_t r_ = (uint32_t)(wm * (MT * 16) + i * 16 + arow);
                    uint32_t sw = SW128(r_ * 128 + (uint32_t)(s * 16 + akof) * 2);
                    ldsm_x4(ah[i][0], ah[i][1], ah[i][2], ah[i][3], tb + sw);
                    if (PASSES == 3)
                        ldsm_x4(al[i][0], al[i][1], al[i][2], al[i][3],
                                tb + A_T + sw);
                }
#pragma unroll
                for (int jj = 0; jj < 4; jj += 2) {
                    uint32_t r_ = (uint32_t)(wn * 32 + jj * 8 + brow);
                    uint32_t sw = SW128(r_ * 128 + (uint32_t)(s * 16 + bkof) * 2);
                    ldsm_x4(bh[jj][0], bh[jj][1], bh[jj + 1][0], bh[jj + 1][1],
                            tb + BH_O + sw);
                    if (PASSES == 3)
                        ldsm_x4(bl[jj][0], bl[jj][1], bl[jj + 1][0], bl[jj + 1][1],
                                tb + BL_O + sw);
                }
#pragma unroll
                for (int i = 0; i < MT; i++)
#pragma unroll
                    for (int j = 0; j < 4; j++) {
                        mma_bf16(acc[i][j], ah[i], bh[j]);
                        if (PASSES == 3) {
                            mma_bf16(acc[i][j], ah[i], bl[j]);
                            mma_bf16(acc[i][j], al[i], bh[j]);
                        }
                    }
            }
            __syncthreads();
        }

        // fused epilogue: relu(h + b1)·W2 per m-row for this n-tile
#pragma unroll
        for (int j = 0; j < 4; j++) {
            int n = nt * BN_ + wn * 32 + j * 8 + (l & 3) * 2;
            float b1a = __ldg(&b1[n]), b1b = __ldg(&b1[n + 1]);
            float w2a = __ldg(&W2[n]), w2b = __ldg(&W2[n + 1]);
#pragma unroll
            for (int i = 0; i < MT; i++) {
                rowacc[i][0] += fmaxf(acc[i][j][0] + b1a, 0.f) * w2a
                              + fmaxf(acc[i][j][1] + b1b, 0.f) * w2b;
                rowacc[i][1] += fmaxf(acc[i][j][2] + b1a, 0.f) * w2a
                              + fmaxf(acc[i][j][3] + b1b, 0.f) * w2b;
            }
        }
    }

    // reduce across (l&3) lanes, then across the 4 n-warps via smem
#pragma unroll
    for (int i = 0; i < MT; i++)
#pragma unroll
        for (int p = 0; p < 2; p++) {
            float v = rowacc[i][p];
            v += __shfl_xor_sync(0xffffffffu, v, 1);
            v += __shfl_xor_sync(0xffffffffu, v, 2);
            if ((l & 3) == 0)
                red[wm * (MT * 16) + i * 16 + (l >> 2) + p * 8][wn] = v;
        }
    __syncthreads();
    if (t < BMp)
        atomicAdd(&outp[m0 + t],
                  red[t][0] + red[t][1] + red[t][2] + red[t][3]);
}

// ------------------------- kernel: topk + collect + gather (merged) ---------
__global__ void topk_collect_gather_kernel(const float* __restrict__ X) {
    __shared__ float s[S_];
    __shared__ int hist[256];
    __shared__ int sel_bin, rem_s;
    __shared__ float cutsh;
    __shared__ int scnt;
    const int row = blockIdx.x;
    const int t = threadIdx.x;
    const uint32_t rk0 = g_rng2k[0], rk1 = g_rng2k[1];
    for (int i = t; i < S_; i += blockDim.x) {
        int gi = row * S_ + i;
        s[i] = g_pert[gi] + jax_gumbel(rk0, rk1, (uint32_t)gi, (uint32_t)M_);
        g_sel[gi] = 0;
    }
    if (t < CMAX) g_cand_logit[row * CMAX + t] = 0.f;   // refine accumulators
    __syncthreads();

    uint32_t prefix = 0;
    int remaining = g_ksel;
#pragma unroll
    for (int level = 0; level < 4; level++) {
        const int shift = 24 - 8 * level;
        if (t < 256) hist[t] = 0;
        __syncthreads();
        for (int i = t; i < S_; i += blockDim.x) {
            uint32_t b = __float_as_uint(s[i]);
            uint32_t u = b ^ ((b & 0x80000000u) ? 0xFFFFFFFFu : 0x80000000u);
            bool ok = (level == 0) || ((u >> (shift + 8)) == prefix);
            if (ok) atomicAdd(&hist[(u >> shift) & 0xFFu], 1);
        }
        __syncthreads();
        if (t == 0) {
            int cum = 0, b = 255;
            for (; b > 0; b--) {
                int c = hist[b];
                if (cum + c >= remaining) break;
                cum += c;
            }
            sel_bin = b;
            rem_s = remaining - cum;
        }
        __syncthreads();
        prefix = (prefix << 8) | (uint32_t)sel_bin;
        remaining = rem_s;
        __syncthreads();
    }
    if (t == 0) {
        uint32_t u = prefix;
        uint32_t b = (u & 0x80000000u) ? (u ^ 0x80000000u) : (u ^ 0xFFFFFFFFu);
        cutsh = __uint_as_float(b) - DELTA;
        scnt = 0;
    }
    __syncthreads();
    for (int i = t; i < S_; i += blockDim.x) {
        if (s[i] >= cutsh) {
            int pos = atomicAdd(&scnt, 1);
            if (pos < CMAX) g_cand_idx[row * CMAX + pos] = row * S_ + i;
        }
    }
    __syncthreads();
    const int cnt = (scnt < CMAX) ? scnt : CMAX;
    if (t == 0) g_cand_cnt[row] = cnt;

    // gather + bf16-split candidate rows (128 work items per candidate row)
    for (int w = t; w < cnt * 128; w += blockDim.x) {
        int c  = w >> 7;
        int e0 = (w & 127) * 8;
        int tok = g_cand_idx[row * CMAX + c];
        const float* src = X + (size_t)tok * D_ + e0;
        __nv_bfloat16* dh = g_Chi + (size_t)(row * CMAX + c) * D_ + e0;
        __nv_bfloat16* dl = g_Clo + (size_t)(row * CMAX + c) * D_ + e0;
#pragma unroll
        for (int e = 0; e < 8; e += 4) {
            float4 v = *(const float4*)(src + e);
            __nv_bfloat16 h0 = __float2bfloat16(v.x), h1 = __float2bfloat16(v.y);
            __nv_bfloat16 h2 = __float2bfloat16(v.z), h3 = __float2bfloat16(v.w);
            __nv_bfloat16 l0 = __float2bfloat16(v.x - __bfloat162float(h0));
            __nv_bfloat16 l1 = __float2bfloat16(v.y - __bfloat162float(h1));
            __nv_bfloat16 l2 = __float2bfloat16(v.z - __bfloat162float(h2));
            __nv_bfloat16 l3 = __float2bfloat16(v.w - __bfloat162float(h3));
            __nv_bfloat162 hp0 = {h0, h1}, hp1 = {h2, h3};
            __nv_bfloat162 lp0 = {l0, l1}, lp1 = {l2, l3};
            *(uint2*)(dh + e) = make_uint2(*(uint32_t*)&hp0, *(uint32_t*)&hp1);
            *(uint2*)(dl + e) = make_uint2(*(uint32_t*)&lp0, *(uint32_t*)&lp1);
        }
    }
}

// ------------------------- kernel: final exact top-k ------------------------
__global__ void final_select_kernel() {
    __shared__ float v[CMAX];
    int r = blockIdx.x;
    int t = threadIdx.x;
    int cnt = g_cand_cnt[r];
    int tok = -1;
    float val = -1e30f;
    if (t < cnt) {
        tok = g_cand_idx[r * CMAX + t];
        val = g_cand_logit[r * CMAX + t]
            + jax_gumbel(g_rng2k[0], g_rng2k[1], (uint32_t)tok, (uint32_t)M_);
    }
    v[t] = val;
    __syncthreads();
    for (int k = 2; k <= CMAX; k <<= 1) {
        for (int j = k >> 1; j > 0; j >>= 1) {
            int ixj = t ^ j;
            if (ixj > t) {
                bool up = ((t & k) == 0);
                float a = v[t], b = v[ixj];
                if ((a > b) == up) { v[t] = b; v[ixj] = a; }
            }
            __syncthreads();
        }
    }
    float th = v[CMAX - g_ksel];   // k-th largest
    __syncthreads();
    if (t < cnt && val >= th) g_sel[tok] = 1;
}

// ------------------------- kernel: copy selected rows + mask ----------------
__global__ void copy_out_kernel(const float* __restrict__ X,
                                float* __restrict__ out) {
    int r = blockIdx.x / CMAX;
    int c = blockIdx.x % CMAX;
    if (c >= g_cand_cnt[r]) return;
    int tok = g_cand_idx[r * CMAX + c];
    if (!g_sel[tok]) return;
    float4* dst = (float4*)(out + (size_t)tok * D_);
    const float4* src = (const float4*)(X + (size_t)tok * D_);
    dst[threadIdx.x] = src[threadIdx.x];
    if (threadIdx.x == 0) out[OUT_MASK_OFF + tok] = 1.0f;
}

// ============================================================================
extern "C" void kernel_launch(void* const* d_in, const int* in_sizes, int n_in,
                              void* d_out, int out_size) {
    const float* X        = (const float*)d_in[0];
    const float* W1       = (const float*)d_in[1];
    const float* b1       = (const float*)d_in[2];
    const float* W2       = (const float*)d_in[3];
    const float* k_logits = (const float*)d_in[5];
    float* out = (float*)d_out;

    auto* gemm_main   = gemm_kernel<1, 128, 2, 2>;   // grid (256, 8)
    auto* gemm_refine = gemm_kernel<3, 64, 1, 2>;    // grid (16, 16)

    static void *p_xhi = nullptr, *p_chi, *p_clo, *p_pert, *p_clog;
    static cudaStream_t s2 = nullptr;
    static cudaEvent_t evFork, evW, evZ;
    if (!p_xhi) {
        cudaGetSymbolAddress(&p_xhi,  g_Xhi);
        cudaGetSymbolAddress(&p_chi,  g_Chi);
        cudaGetSymbolAddress(&p_clo,  g_Clo);
        cudaGetSymbolAddress(&p_pert, g_pert);
        cudaGetSymbolAddress(&p_clog, g_cand_logit);
        cudaFuncSetAttribute(gemm_main,
                             cudaFuncAttributeMaxDynamicSharedMemorySize, SMEM_MAIN);
        cudaFuncSetAttribute(gemm_refine,
                             cudaFuncAttributeMaxDynamicSharedMemorySize, SMEM_REF);
        cudaStreamCreateWithFlags(&s2, cudaStreamNonBlocking);
        cudaEventCreateWithFlags(&evFork, cudaEventDisableTiming);
        cudaEventCreateWithFlags(&evW,    cudaEventDisableTiming);
        cudaEventCreateWithFlags(&evZ,    cudaEventDisableTiming);
    }

    // ---- fork side stream: W1 prep + k-select + output zeroing -------------
    cudaEventRecord(evFork, 0);
    cudaStreamWaitEvent(s2, evFork, 0);
    convert_w1_kernel<<<dim3(H_ / 32, D_ / 32), 256, 0, s2>>>(W1);
    k_select_kernel<<<1, 64, 0, s2>>>(k_logits, out + OUT_EK_OFF);
    cudaEventRecord(evW, s2);
    zero_out_kernel<<<32800, 256, 0, s2>>>(out);   // runs under the GEMM
    cudaEventRecord(evZ, s2);

    // ---- main stream --------------------------------------------------------
    convert_x_kernel<<<(M_ * D_ / 8) / 256, 256>>>(X);
    cudaStreamWaitEvent(0, evW, 0);                 // need W1t + rng2k + ksel
    gemm_main<<<dim3(M_ / 128, NSPLIT), 256, SMEM_MAIN>>>(
        (const __nv_bfloat16*)p_xhi, nullptr, b1, W2, (float*)p_pert);
    topk_collect_gather_kernel<<<B_, 1024>>>(X);
    gemm_refine<<<dim3(CTOT / 64, NNT), 256, SMEM_REF>>>(
        (const __nv_bfloat16*)p_chi, (const __nv_bfloat16*)p_clo,
        b1, W2, (float*)p_clog);
    final_select_kernel<<<B_, CMAX>>>();
    cudaStreamWaitEvent(0, evZ, 0);                 // zeros in place
    copy_out_kernel<<<B_ * CMAX, 256>>>(X, out);
}

// round 14
// speedup vs baseline: 1.0585x; 1.0196x over previous
#include <cuda_runtime.h>
#include <cuda_bf16.h>
#include <cstdint>

// ============================================================================
// AdaptiveTokenFilter — GB300 sm_103a — 1-pass bf16 HMMA + exact 3-pass refine
// R14: convert_x 4x ILP; zero_out descheduled off convert_x's DRAM window
// (waits evCX, runs under GEMM); k_select moved off the GEMM wait path.
// ============================================================================

#define B_ 8
#define S_ 4096
#define D_ 1024
#define H_ 2048
#define M_ (B_ * S_)            // 32768 tokens
#define MAXK 64
#define CMAX 128                // max candidates per row
#define CTOT (B_ * CMAX)        // 1024 compact rows
#define DELTA 0.1f              // candidate window (>=8x max 1-pass error)

#define OUT_MASK_OFF ((size_t)M_ * D_)
#define OUT_EK_OFF   ((size_t)M_ * D_ + M_)

#define THREEFRY_PARTITIONABLE 1

// GEMM tiling
#define BN_ 128
#define BK_ 64
#define NNT (H_ / BN_)          // 16 n-tiles
#define NKC (D_ / BK_)          // 16 k-chunks
#define NSPLIT 8                // main GEMM n-split

// dynamic smem per instantiation (2 stages + 1KB align slack)
#define SMEM_MAIN (2 * (128 * 128 + 16384) + 1024)          // 66560
#define SMEM_REF  (2 * (2 * 64 * 128 + 2 * 16384) + 1024)   // 99328

#define SW128(bo) ((bo) ^ (((bo) >> 3) & 0x70))

// ------------------------- device scratch (no allocs) -----------------------
__device__ __nv_bfloat16 g_Xhi[(size_t)M_ * D_];
__device__ __nv_bfloat16 g_W1thi[(size_t)H_ * D_];
__device__ __nv_bfloat16 g_W1tlo[(size_t)H_ * D_];
__device__ __nv_bfloat16 g_Chi[(size_t)CTOT * D_];
__device__ __nv_bfloat16 g_Clo[(size_t)CTOT * D_];
__device__ float    g_pert[M_];            // main: logit partials (atomic)
__device__ float    g_cand_logit[CTOT];
__device__ int      g_cand_idx[CTOT];      // global token ids
__device__ int      g_cand_cnt[B_];
__device__ unsigned char g_sel[M_];
__device__ int      g_ksel;
__device__ uint32_t g_rng2k[2];

// ------------------------- PTX helpers --------------------------------------
__device__ __forceinline__ uint32_t smem_u32(const void* p) {
    uint32_t a;
    asm("{ .reg .u64 t; cvta.to.shared.u64 t, %1; cvt.u32.u64 %0, t; }" : "=r"(a) : "l"(p));
    return a;
}
#define CP16(dst, src) \
    asm volatile("cp.async.cg.shared.global [%0], [%1], 16;" \
        :: "r"((uint32_t)(dst)), "l"((const void*)(src)) : "memory")
#define CP_COMMIT() asm volatile("cp.async.commit_group;" ::: "memory")
#define CP_WAIT1()  asm volatile("cp.async.wait_group 1;" ::: "memory")
#define CP_WAIT0()  asm volatile("cp.async.wait_group 0;" ::: "memory")

__device__ __forceinline__ void ldsm_x4(uint32_t& r0, uint32_t& r1,
                                        uint32_t& r2, uint32_t& r3, uint32_t a) {
    asm volatile("ldmatrix.sync.aligned.m8n8.x4.shared.b16 {%0,%1,%2,%3}, [%4];"
                 : "=r"(r0), "=r"(r1), "=r"(r2), "=r"(r3) : "r"(a));
}
__device__ __forceinline__ void mma_bf16(float* c, const uint32_t* a, const uint32_t* b) {
    asm volatile("mma.sync.aligned.m16n8k16.row.col.f32.bf16.bf16.f32 "
                 "{%0,%1,%2,%3}, {%4,%5,%6,%7}, {%8,%9}, {%0,%1,%2,%3};"
                 : "+f"(c[0]), "+f"(c[1]), "+f"(c[2]), "+f"(c[3])
                 : "r"(a[0]), "r"(a[1]), "r"(a[2]), "r"(a[3]), "r"(b[0]), "r"(b[1]));
}

// ------------------------- threefry2x32 (JAX-exact, 20 rounds) --------------
__device__ __forceinline__ uint32_t rotl32(uint32_t v, int r) {
    return (v << r) | (v >> (32 - r));
}
__device__ __forceinline__ void tf_rounds_a(uint32_t& x0, uint32_t& x1) {
    x0 += x1; x1 = rotl32(x1, 13); x1 ^= x0;
    x0 += x1; x1 = rotl32(x1, 15); x1 ^= x0;
    x0 += x1; x1 = rotl32(x1, 26); x1 ^= x0;
    x0 += x1; x1 = rotl32(x1,  6); x1 ^= x0;
}
__device__ __forceinline__ void tf_rounds_b(uint32_t& x0, uint32_t& x1) {
    x0 += x1; x1 = rotl32(x1, 17); x1 ^= x0;
    x0 += x1; x1 = rotl32(x1, 29); x1 ^= x0;
    x0 += x1; x1 = rotl32(x1, 16); x1 ^= x0;
    x0 += x1; x1 = rotl32(x1, 24); x1 ^= x0;
}
__device__ __forceinline__ void threefry2x32(uint32_t k1, uint32_t k2,
                                             uint32_t x0, uint32_t x1,
                                             uint32_t* o0, uint32_t* o1) {
    uint32_t ks2 = k1 ^ k2 ^ 0x1BD11BDAu;
    x0 += k1; x1 += k2;
    tf_rounds_a(x0, x1); x0 += k2;  x1 += ks2 + 1u;
    tf_rounds_b(x0, x1); x0 += ks2; x1 += k1  + 2u;
    tf_rounds_a(x0, x1); x0 += k1;  x1 += k2  + 3u;
    tf_rounds_b(x0, x1); x0 += k2;  x1 += ks2 + 4u;
    tf_rounds_a(x0, x1); x0 += ks2; x1 += k1  + 5u;
    *o0 = x0; *o1 = x1;
}
__device__ __forceinline__ uint32_t jax_random_bits32(uint32_t k1, uint32_t k2,
                                                      uint32_t idx, uint32_t n) {
#if THREEFRY_PARTITIONABLE
    uint32_t o0, o1;
    threefry2x32(k1, k2, 0u, idx, &o0, &o1);
    return o0 ^ o1;
#else
    uint32_t half = n >> 1;
    uint32_t o0, o1;
    if (idx < half) { threefry2x32(k1, k2, idx, idx + half, &o0, &o1); return o0; }
    else            { threefry2x32(k1, k2, idx - half, idx, &o0, &o1); return o1; }
#endif
}
__device__ __forceinline__ float jax_gumbel(uint32_t k1, uint32_t k2,
                                            uint32_t idx, uint32_t n) {
    uint32_t bits = jax_random_bits32(k1, k2, idx, n);
    float f = __uint_as_float((bits >> 9) | 0x3f800000u) - 1.0f;
    const float minv = 1e-8f;
    float u = __fadd_rn(__fmul_rn(f, 1.0f - 1e-8f), minv);
    u = fmaxf(minv, u);
    return -logf(-logf(u));
}

// ------------------------- kernel: X -> bf16 hi (+ zero pert), 4x ILP -------
__global__ void convert_x_kernel(const float* __restrict__ X) {
    if (threadIdx.x < 4) g_pert[blockIdx.x * 4 + threadIdx.x] = 0.f;
    size_t i = ((size_t)blockIdx.x * blockDim.x + threadIdx.x) * 16;
#pragma unroll
    for (int u = 0; u < 2; u++) {
        float4 v0 = *(const float4*)(X + i + u * 8);
        float4 v1 = *(const float4*)(X + i + u * 8 + 4);
        __nv_bfloat162 a0 = {__float2bfloat16(v0.x), __float2bfloat16(v0.y)};
        __nv_bfloat162 a1 = {__float2bfloat16(v0.z), __float2bfloat16(v0.w)};
        __nv_bfloat162 b0 = {__float2bfloat16(v1.x), __float2bfloat16(v1.y)};
        __nv_bfloat162 b1 = {__float2bfloat16(v1.z), __float2bfloat16(v1.w)};
        *(uint4*)&g_Xhi[i + u * 8] = make_uint4(*(uint32_t*)&a0, *(uint32_t*)&a1,
                                                *(uint32_t*)&b0, *(uint32_t*)&b1);
    }
}

// ------------------------- kernel: tiled transpose+split W1 -----------------
__global__ void convert_w1_kernel(const float* __restrict__ W1) {
    __shared__ float tile[32][33];
    const int bn = blockIdx.x;            // H/32 = 64
    const int bk = blockIdx.y;            // D/32 = 32
    const int tx = threadIdx.x & 31;
    const int ty = threadIdx.x >> 5;      // 0..7
#pragma unroll
    for (int i = 0; i < 4; i++) {
        int k = bk * 32 + ty + i * 8;
        tile[ty + i * 8][tx] = W1[(size_t)k * H_ + bn * 32 + tx];
    }
    __syncthreads();
#pragma unroll
    for (int i = 0; i < 4; i++) {
        int n = bn * 32 + ty + i * 8;
        int k = bk * 32 + tx;
        float v = tile[tx][ty + i * 8];
        __nv_bfloat16 h = __float2bfloat16(v);
        __nv_bfloat16 l = __float2bfloat16(v - __bfloat162float(h));
        g_W1thi[(size_t)n * D_ + k] = h;
        g_W1tlo[(size_t)n * D_ + k] = l;
    }
}

// ------------------------- kernel: k-selection path -------------------------
__global__ void k_select_kernel(const float* __restrict__ k_logits,
                                float* __restrict__ out_ek) {
    __shared__ float vals[MAXK];
    __shared__ uint32_t rngs[4];
    if (threadIdx.x == 0) {
        uint32_t a, b;
#if THREEFRY_PARTITIONABLE
        threefry2x32(0u, 42u, 0u, 0u, &a, &b); rngs[0] = a; rngs[1] = b;
        threefry2x32(0u, 42u, 0u, 1u, &a, &b); rngs[2] = a; rngs[3] = b;
#else
        uint32_t a0, b0, a1, b1;
        threefry2x32(0u, 42u, 0u, 2u, &a0, &b0);
        threefry2x32(0u, 42u, 1u, 3u, &a1, &b1);
        rngs[0] = a0; rngs[1] = a1; rngs[2] = b0; rngs[3] = b1;
#endif
        g_rng2k[0] = rngs[2]; g_rng2k[1] = rngs[3];
    }
    __syncthreads();
    int i = threadIdx.x;
    float g = jax_gumbel(rngs[0], rngs[1], (uint32_t)i, MAXK);
    vals[i] = k_logits[i] + g;
    __syncthreads();
    if (i == 0) {
        float mx = vals[0]; int am = 0;
        for (int j = 1; j < MAXK; j++)
            if (vals[j] > mx) { mx = vals[j]; am = j; }
        float sum = 0.f, ek = 0.f;
        for (int j = 0; j < MAXK; j++) {
            float e = expf(vals[j] - mx);
            sum += e; ek += e * (float)(j + 1);
        }
        g_ksel = am + 1;
        out_ek[0] = ek / sum;
    }
}

// ------------------------- kernel: zero output (emb + mask) -----------------
__global__ void zero_out_kernel(float* __restrict__ out) {
    size_t i = ((size_t)blockIdx.x * 256 + threadIdx.x) * 4;
    *(float4*)(out + i) = make_float4(0.f, 0.f, 0.f, 0.f);
}

// ------------------------- templated HMMA GEMM (R10 2-stage core) -----------
template<int PASSES, int BMp, int NT_CHUNK, int MINB>
__global__ void __launch_bounds__(256, MINB)
gemm_kernel(const __nv_bfloat16* __restrict__ Ahi,
            const __nv_bfloat16* __restrict__ Alo,
            const float* __restrict__ b1,
            const float* __restrict__ W2,
            float* __restrict__ outp) {
    extern __shared__ char dyn_smem[];
    __shared__ float red[BMp][4];

    constexpr int MT = BMp / 32;
    constexpr uint32_t A_T  = (uint32_t)BMp * 128;
    constexpr uint32_t BH_O = (PASSES == 3) ? 2 * A_T : A_T;
    constexpr uint32_t BL_O = BH_O + 16384;
    constexpr uint32_t BUFB = BH_O + ((PASSES == 3) ? 2 : 1) * 16384;
    constexpr int AI = BMp * 8 / 256;

    const uint32_t braw = smem_u32(dyn_smem);
    const uint32_t base = (braw + 1023u) & ~1023u;

    const int t   = threadIdx.x;
    const int l   = t & 31;
    const int wid = t >> 5;
    const int wm  = wid >> 2;
    const int wn  = wid & 3;
    const int m0  = blockIdx.x * BMp;

    float rowacc[MT][2];
#pragma unroll
    for (int i = 0; i < MT; i++) { rowacc[i][0] = 0.f; rowacc[i][1] = 0.f; }

    const int arow = (l & 15);
    const int akof = (l >> 4) * 8;
    const int brow = ((l >> 4) & 1) * 8 + (l & 7);
    const int bkof = ((l >> 3) & 1) * 8;

    auto load_tiles = [&](int buf, int nt, int kc) {
        const uint32_t tb = base + (uint32_t)buf * BUFB;
        const size_t ak = (size_t)kc * BK_;
#pragma unroll
        for (int it = 0; it < AI; it++) {
            int idx = t + it * 256;
            int r = idx >> 3;
            int c = idx & 7;
            uint32_t sw = SW128((uint32_t)(r * 128 + c * 16));
            size_t aoff = (size_t)(m0 + r) * D_ + ak + c * 8;
            CP16(tb + sw, Ahi + aoff);
            if (PASSES == 3) CP16(tb + A_T + sw, Alo + aoff);
        }
#pragma unroll
        for (int it = 0; it < 4; it++) {
            int idx = t + it * 256;
            int r = idx >> 3;
            int c = idx & 7;
            uint32_t sw = SW128((uint32_t)(r * 128 + c * 16));
            size_t boff = (size_t)(nt * BN_ + r) * D_ + ak + c * 8;
            CP16(tb + BH_O + sw, g_W1thi + boff);
            if (PASSES == 3) CP16(tb + BL_O + sw, g_W1tlo + boff);
        }
    };

    for (int nti = 0; nti < NT_CHUNK; nti++) {
        const int nt = blockIdx.y * NT_CHUNK + nti;
        float acc[MT][4][4];
#pragma unroll
        for (int i = 0; i < MT; i++)
#pragma unroll
            for (int j = 0; j < 4; j++)
#pragma unroll
                for (int q = 0; q < 4; q++) acc[i][j][q] = 0.f;

        load_tiles(0, nt, 0);
        CP_COMMIT();

        for (int kc = 0; kc < NKC; kc++) {
            if (kc < NKC - 1) {
                load_tiles((kc + 1) & 1, nt, kc + 1);
                CP_COMMIT();
                CP_WAIT1();
            } else {
                CP_WAIT0();
            }
            __syncthreads();

            const uint32_t tb = base + (uint32_t)(kc & 1) * BUFB;
#pragma unroll
            for (int s = 0; s < 4; s++) {
                uint32_t ah[MT][4], al[MT][4], bh[4][2], bl[4][2];
#pragma unroll
                for (int i = 0; i < MT; i++) {
                    uint32_t r_ = (uint32_t)(wm * (MT * 16) + i * 16 + arow);
                    uint32_t sw = SW128(r_ * 128 + (uint32_t)(s * 16 + akof) * 2);
                    ldsm_x4(ah[i][0], ah[i][1], ah[i][2], ah[i][3], tb + sw);
                    if (PASSES == 3)
                        ldsm_x4(al[i][0], al[i][1], al[i][2], al[i][3],
                                tb + A_T + sw);
                }
#pragma unroll
                for (int jj = 0; jj < 4; jj += 2) {
                    uint32_t r_ = (uint32_t)(wn * 32 + jj * 8 + brow);
                    uint32_t sw = SW128(r_ * 128 + (uint32_t)(s * 16 + bkof) * 2);
                    ldsm_x4(bh[jj][0], bh[jj][1], bh[jj + 1][0], bh[jj + 1][1],
                            tb + BH_O + sw);
                    if (PASSES == 3)
                        ldsm_x4(bl[jj][0], bl[jj][1], bl[jj + 1][0], bl[jj + 1][1],
                                tb + BL_O + sw);
                }
#pragma unroll
                for (int i = 0; i < MT; i++)
#pragma unroll
                    for (int j = 0; j < 4; j++) {
                        mma_bf16(acc[i][j], ah[i], bh[j]);
                        if (PASSES == 3) {
                            mma_bf16(acc[i][j], ah[i], bl[j]);
                            mma_bf16(acc[i][j], al[i], bh[j]);
                        }
                    }
            }
            __syncthreads();
        }

        // fused epilogue: relu(h + b1)·W2 per m-row for this n-tile
#pragma unroll
        for (int j = 0; j < 4; j++) {
            int n = nt * BN_ + wn * 32 + j * 8 + (l & 3) * 2;
            float b1a = __ldg(&b1[n]), b1b = __ldg(&b1[n + 1]);
            float w2a = __ldg(&W2[n]), w2b = __ldg(&W2[n + 1]);
#pragma unroll
            for (int i = 0; i < MT; i++) {
                rowacc[i][0] += fmaxf(acc[i][j][0] + b1a, 0.f) * w2a
                              + fmaxf(acc[i][j][1] + b1b, 0.f) * w2b;
                rowacc[i][1] += fmaxf(acc[i][j][2] + b1a, 0.f) * w2a
                              + fmaxf(acc[i][j][3] + b1b, 0.f) * w2b;
            }
        }
    }

    // reduce across (l&3) lanes, then across the 4 n-warps via smem
#pragma unroll
    for (int i = 0; i < MT; i++)
#pragma unroll
        for (int p = 0; p < 2; p++) {
            float v = rowacc[i][p];
            v += __shfl_xor_sync(0xffffffffu, v, 1);
            v += __shfl_xor_sync(0xffffffffu, v, 2);
            if ((l & 3) == 0)
                red[wm * (MT * 16) + i * 16 + (l >> 2) + p * 8][wn] = v;
        }
    __syncthreads();
    if (t < BMp)
        atomicAdd(&outp[m0 + t],
                  red[t][0] + red[t][1] + red[t][2] + red[t][3]);
}

// ------------------------- kernel: topk + collect + gather (merged) ---------
__global__ void topk_collect_gather_kernel(const float* __restrict__ X) {
    __shared__ float s[S_];
    __shared__ int hist[256];
    __shared__ int sel_bin, rem_s;
    __shared__ float cutsh;
    __shared__ int scnt;
    const int row = blockIdx.x;
    const int t = threadIdx.x;
    const uint32_t rk0 = g_rng2k[0], rk1 = g_rng2k[1];
    for (int i = t; i < S_; i += blockDim.x) {
        int gi = row * S_ + i;
        s[i] = g_pert[gi] + jax_gumbel(rk0, rk1, (uint32_t)gi, (uint32_t)M_);
        g_sel[gi] = 0;
    }
    if (t < CMAX) g_cand_logit[row * CMAX + t] = 0.f;   // refine accumulators
    __syncthreads();

    uint32_t prefix = 0;
    int remaining = g_ksel;
#pragma unroll
    for (int level = 0; level < 4; level++) {
        const int shift = 24 - 8 * level;
        if (t < 256) hist[t] = 0;
        __syncthreads();
        for (int i = t; i < S_; i += blockDim.x) {
            uint32_t b = __float_as_uint(s[i]);
            uint32_t u = b ^ ((b & 0x80000000u) ? 0xFFFFFFFFu : 0x80000000u);
            bool ok = (level == 0) || ((u >> (shift + 8)) == prefix);
            if (ok) atomicAdd(&hist[(u >> shift) & 0xFFu], 1);
        }
        __syncthreads();
        if (t == 0) {
            int cum = 0, b = 255;
            for (; b > 0; b--) {
                int c = hist[b];
                if (cum + c >= remaining) break;
                cum += c;
            }
            sel_bin = b;
            rem_s = remaining - cum;
        }
        __syncthreads();
        prefix = (prefix << 8) | (uint32_t)sel_bin;
        remaining = rem_s;
        __syncthreads();
    }
    if (t == 0) {
        uint32_t u = prefix;
        uint32_t b = (u & 0x80000000u) ? (u ^ 0x80000000u) : (u ^ 0xFFFFFFFFu);
        cutsh = __uint_as_float(b) - DELTA;
        scnt = 0;
    }
    __syncthreads();
    for (int i = t; i < S_; i += blockDim.x) {
        if (s[i] >= cutsh) {
            int pos = atomicAdd(&scnt, 1);
            if (pos < CMAX) g_cand_idx[row * CMAX + pos] = row * S_ + i;
        }
    }
    __syncthreads();
    const int cnt = (scnt < CMAX) ? scnt : CMAX;
    if (t == 0) g_cand_cnt[row] = cnt;

    // gather + bf16-split candidate rows (128 work items per candidate row)
    for (int w = t; w < cnt * 128; w += blockDim.x) {
        int c  = w >> 7;
        int e0 = (w & 127) * 8;
        int tok = g_cand_idx[row * CMAX + c];
        const float* src = X + (size_t)tok * D_ + e0;
        __nv_bfloat16* dh = g_Chi + (size_t)(row * CMAX + c) * D_ + e0;
        __nv_bfloat16* dl = g_Clo + (size_t)(row * CMAX + c) * D_ + e0;
#pragma unroll
        for (int e = 0; e < 8; e += 4) {
            float4 v = *(const float4*)(src + e);
            __nv_bfloat16 h0 = __float2bfloat16(v.x), h1 = __float2bfloat16(v.y);
            __nv_bfloat16 h2 = __float2bfloat16(v.z), h3 = __float2bfloat16(v.w);
            __nv_bfloat16 l0 = __float2bfloat16(v.x - __bfloat162float(h0));
            __nv_bfloat16 l1 = __float2bfloat16(v.y - __bfloat162float(h1));
            __nv_bfloat16 l2 = __float2bfloat16(v.z - __bfloat162float(h2));
            __nv_bfloat16 l3 = __float2bfloat16(v.w - __bfloat162float(h3));
            __nv_bfloat162 hp0 = {h0, h1}, hp1 = {h2, h3};
            __nv_bfloat162 lp0 = {l0, l1}, lp1 = {l2, l3};
            *(uint2*)(dh + e) = make_uint2(*(uint32_t*)&hp0, *(uint32_t*)&hp1);
            *(uint2*)(dl + e) = make_uint2(*(uint32_t*)&lp0, *(uint32_t*)&lp1);
        }
    }
}

// ------------------------- kernel: final exact top-k ------------------------
__global__ void final_select_kernel() {
    __shared__ float v[CMAX];
    int r = blockIdx.x;
    int t = threadIdx.x;
    int cnt = g_cand_cnt[r];
    int tok = -1;
    float val = -1e30f;
    if (t < cnt) {
        tok = g_cand_idx[r * CMAX + t];
        val = g_cand_logit[r * CMAX + t]
            + jax_gumbel(g_rng2k[0], g_rng2k[1], (uint32_t)tok, (uint32_t)M_);
    }
    v[t] = val;
    __syncthreads();
    for (int k = 2; k <= CMAX; k <<= 1) {
        for (int j = k >> 1; j > 0; j >>= 1) {
            int ixj = t ^ j;
            if (ixj > t) {
                bool up = ((t & k) == 0);
                float a = v[t], b = v[ixj];
                if ((a > b) == up) { v[t] = b; v[ixj] = a; }
            }
            __syncthreads();
        }
    }
    float th = v[CMAX - g_ksel];   // k-th largest
    __syncthreads();
    if (t < cnt && val >= th) g_sel[tok] = 1;
}

// ------------------------- kernel: copy selected rows + mask ----------------
__global__ void copy_out_kernel(const float* __restrict__ X,
                                float* __restrict__ out) {
    int r = blockIdx.x / CMAX;
    int c = blockIdx.x % CMAX;
    if (c >= g_cand_cnt[r]) return;
    int tok = g_cand_idx[r * CMAX + c];
    if (!g_sel[tok]) return;
    float4* dst = (float4*)(out + (size_t)tok * D_);
    const float4* src = (const float4*)(X + (size_t)tok * D_);
    dst[threadIdx.x] = src[threadIdx.x];
    if (threadIdx.x == 0) out[OUT_MASK_OFF + tok] = 1.0f;
}

// ============================================================================
extern "C" void kernel_launch(void* const* d_in, const int* in_sizes, int n_in,
                              void* d_out, int out_size) {
    const float* X        = (const float*)d_in[0];
    const float* W1       = (const float*)d_in[1];
    const float* b1       = (const float*)d_in[2];
    const float* W2       = (const float*)d_in[3];
    const float* k_logits = (const float*)d_in[5];
    float* out = (float*)d_out;

    auto* gemm_main   = gemm_kernel<1, 128, 2, 2>;   // grid (256, 8)
    auto* gemm_refine = gemm_kernel<3, 64, 1, 2>;    // grid (16, 16)

    static void *p_xhi = nullptr, *p_chi, *p_clo, *p_pert, *p_clog;
    static cudaStream_t s2 = nullptr;
    static cudaEvent_t evFork, evW, evZ, evCX;
    if (!p_xhi) {
        cudaGetSymbolAddress(&p_xhi,  g_Xhi);
        cudaGetSymbolAddress(&p_chi,  g_Chi);
        cudaGetSymbolAddress(&p_clo,  g_Clo);
        cudaGetSymbolAddress(&p_pert, g_pert);
        cudaGetSymbolAddress(&p_clog, g_cand_logit);
        cudaFuncSetAttribute(gemm_main,
                             cudaFuncAttributeMaxDynamicSharedMemorySize, SMEM_MAIN);
        cudaFuncSetAttribute(gemm_refine,
                             cudaFuncAttributeMaxDynamicSharedMemorySize, SMEM_REF);
        cudaStreamCreateWithFlags(&s2, cudaStreamNonBlocking);
        cudaEventCreateWithFlags(&evFork, cudaEventDisableTiming);
        cudaEventCreateWithFlags(&evW,    cudaEventDisableTiming);
        cudaEventCreateWithFlags(&evZ,    cudaEventDisableTiming);
        cudaEventCreateWithFlags(&evCX,   cudaEventDisableTiming);
    }

    // ---- fork side stream: W1 prep; then (after convert_x) ksel + zeroing --
    cudaEventRecord(evFork, 0);
    cudaStreamWaitEvent(s2, evFork, 0);
    convert_w1_kernel<<<dim3(H_ / 32, D_ / 32), 256, 0, s2>>>(W1);
    cudaEventRecord(evW, s2);                       // GEMM needs only W1t-hi
    k_select_kernel<<<1, 64, 0, s2>>>(k_logits, out + OUT_EK_OFF);

    // ---- main stream --------------------------------------------------------
    convert_x_kernel<<<(M_ * D_ / 16) / 256, 256>>>(X);
    cudaEventRecord(evCX, 0);
    // zero_out waits for convert_x so it doesn't steal its DRAM bandwidth;
    // it then runs fully under the (DRAM-idle) GEMM.
    cudaStreamWaitEvent(s2, evCX, 0);
    zero_out_kernel<<<32800, 256, 0, s2>>>(out);
    cudaEventRecord(evZ, s2);

    cudaStreamWaitEvent(0, evW, 0);                 // need W1t (hi)
    gemm_main<<<dim3(M_ / 128, NSPLIT), 256, SMEM_MAIN>>>(
        (const __nv_bfloat16*)p_xhi, nullptr, b1, W2, (float*)p_pert);
    topk_collect_gather_kernel<<<B_, 1024>>>(X);    // also needs ksel/rng (s2, done)
    gemm_refine<<<dim3(CTOT / 64, NNT), 256, SMEM_REF>>>(
        (const __nv_bfloat16*)p_chi, (const __nv_bfloat16*)p_clo,
        b1, W2, (float*)p_clog);
    final_select_kernel<<<B_, CMAX>>>();
    cudaStreamWaitEvent(0, evZ, 0);                 // zeros in place
    copy_out_kernel<<<B_ * CMAX, 256>>>(X, out);
}